// round 8
// baseline (speedup 1.0000x reference)
#include <cuda_runtime.h>
#include <cuda_fp16.h>
#include <stdint.h>
#include <math.h>

#define BQ 2
#define LQ 5000
#define CIN 256
#define DLOI 128
#define NPTS0 32
#define NPTS1 8
#define HH 256
#define HALF 64
#define HW (HH*HH)
#define EPSBN 1e-5f

// ---------------- scratch (device globals; no allocation allowed) ----------------
__device__ __half g_xh[BQ * HW * DLOI];        // fc1 output, NHWC, fp16 (33.5 MB)
__device__ float g_wfc1T[CIN * DLOI];          // [k][o], tf32-rounded
__device__ float g_c1wT[DLOI * HALF];          // [c][o]
__device__ float g_c2wT[HALF * 3 * HALF];      // [(i*3+dk)][o]
__device__ float g_c3wT[HALF * DLOI];          // [i][o]
__device__ float g_bn1s[DLOI], g_bn1t[DLOI];
__device__ float g_bn2s[HALF], g_bn2t[HALF];
__device__ float g_bn3s[HALF], g_bn3t[HALF];

__device__ __forceinline__ float to_tf32(float x) {
    uint32_t r;
    asm("cvt.rna.tf32.f32 %0, %1;" : "=r"(r) : "f"(x));
    return __uint_as_float(r);
}

// ---------------- prep: transpose weights, fold BN ----------------
__global__ void prep_kernel(const float* __restrict__ w_fc1,
                            const float* __restrict__ bn1,
                            const float* __restrict__ c1w,
                            const float* __restrict__ bn2,
                            const float* __restrict__ c2w,
                            const float* __restrict__ bn3,
                            const float* __restrict__ c3w)
{
    int t = blockIdx.x * blockDim.x + threadIdx.x;
    int stride = gridDim.x * blockDim.x;
    for (int idx = t; idx < DLOI * CIN; idx += stride) {
        int o = idx / CIN, k = idx % CIN;
        g_wfc1T[k * DLOI + o] = to_tf32(w_fc1[idx]);
    }
    for (int idx = t; idx < HALF * DLOI; idx += stride) {
        int o = idx / DLOI, c = idx % DLOI;
        g_c1wT[c * HALF + o] = c1w[idx];
    }
    for (int idx = t; idx < HALF * HALF * 3; idx += stride) {
        int o = idx / (HALF * 3), r = idx % (HALF * 3);
        g_c2wT[r * HALF + o] = c2w[idx];
    }
    for (int idx = t; idx < DLOI * HALF; idx += stride) {
        int o = idx / HALF, i = idx % HALF;
        g_c3wT[i * DLOI + o] = c3w[idx];
    }
    for (int idx = t; idx < DLOI; idx += stride) {
        float g = bn1[idx], be = bn1[DLOI + idx], mu = bn1[2*DLOI + idx], va = bn1[3*DLOI + idx];
        float s = g * rsqrtf(va + EPSBN);
        g_bn1s[idx] = s; g_bn1t[idx] = be - mu * s;
    }
    for (int idx = t; idx < HALF; idx += stride) {
        float g = bn2[idx], be = bn2[HALF + idx], mu = bn2[2*HALF + idx], va = bn2[3*HALF + idx];
        float s = g * rsqrtf(va + EPSBN);
        g_bn2s[idx] = s; g_bn2t[idx] = be - mu * s;
        float g3 = bn3[idx], be3 = bn3[HALF + idx], mu3 = bn3[2*HALF + idx], va3 = bn3[3*HALF + idx];
        float s3 = g3 * rsqrtf(va3 + EPSBN);
        g_bn3s[idx] = s3; g_bn3t[idx] = be3 - mu3 * s3;
    }
}

// ---------------- fc1 GEMM via tf32 mma.sync + cp.async double buffering ----------
#define KT 32                   // k per smem stage
#define AS_STRIDE 132           // 128 + 4 pad (words)
#define OSH 136                 // epilogue half staging stride (halves)
#define STAGE_FLOATS (2 * KT * AS_STRIDE)
#define FC1_SMEM (2 * STAGE_FLOATS * 4)

__device__ __forceinline__ void cp_async16(void* smem_ptr, const void* gmem_ptr) {
    uint32_t s = (uint32_t)__cvta_generic_to_shared(smem_ptr);
    asm volatile("cp.async.cg.shared.global [%0], [%1], 16;\n" :: "r"(s), "l"(gmem_ptr));
}

__device__ __forceinline__ void mma_tf32(float4& d, const float* a, const float* b) {
    asm volatile(
        "mma.sync.aligned.m16n8k8.row.col.f32.tf32.tf32.f32 "
        "{%0,%1,%2,%3}, {%4,%5,%6,%7}, {%8,%9}, {%0,%1,%2,%3};\n"
        : "+f"(d.x), "+f"(d.y), "+f"(d.z), "+f"(d.w)
        : "r"(__float_as_uint(a[0])), "r"(__float_as_uint(a[1])),
          "r"(__float_as_uint(a[2])), "r"(__float_as_uint(a[3])),
          "r"(__float_as_uint(b[0])), "r"(__float_as_uint(b[1])));
}

__global__ __launch_bounds__(256) void fc1_gemm_tf32(const float* __restrict__ feat,
                                                     const float* __restrict__ bfc1)
{
    extern __shared__ float sm[];

    int b  = blockIdx.y;
    int p0 = blockIdx.x * 128;
    const float* A = feat + (size_t)b * CIN * HW;
    __half* O = g_xh + (size_t)b * HW * DLOI;

    int t    = threadIdx.x;
    int w    = t >> 5;
    int lane = t & 31;
    int g    = lane >> 2;        // 0..7
    int tg   = lane & 3;         // 0..3
    int warp_m = w & 3;          // 0..3
    int warp_n = w >> 2;         // 0..1
    int m_base = warp_m * 32;
    int n_base = warp_n * 64;

    float4 acc[2][8];
#pragma unroll
    for (int mi = 0; mi < 2; mi++)
#pragma unroll
        for (int ni = 0; ni < 8; ni++) acc[mi][ni] = make_float4(0.f, 0.f, 0.f, 0.f);

    auto issue_stage = [&](int s) {
        float* As = sm + (s & 1) * STAGE_FLOATS;
        float* Bs = As + KT * AS_STRIDE;
        int k0 = s * KT;
#pragma unroll
        for (int i = 0; i < 4; i++) {
            int f  = t + 256 * i;          // 0..1023 float4 index
            int kk = f >> 5;
            int pm = (f & 31) * 4;
            cp_async16(&As[kk * AS_STRIDE + pm], &A[(size_t)(k0 + kk) * HW + p0 + pm]);
            cp_async16(&Bs[kk * AS_STRIDE + pm], &g_wfc1T[(k0 + kk) * DLOI + pm]);
        }
        asm volatile("cp.async.commit_group;\n");
    };

    issue_stage(0);

    const int NS = CIN / KT;     // 8
    for (int s = 0; s < NS; s++) {
        if (s + 1 < NS) {
            issue_stage(s + 1);
            asm volatile("cp.async.wait_group 1;\n");
        } else {
            asm volatile("cp.async.wait_group 0;\n");
        }
        __syncthreads();

        float* As = sm + (s & 1) * STAGE_FLOATS;
        float* Bs = As + KT * AS_STRIDE;

#pragma unroll
        for (int ks = 0; ks < KT / 8; ks++) {
            int kb = ks * 8;
            float afr[2][4];
#pragma unroll
            for (int mi = 0; mi < 2; mi++) {
                int r = m_base + mi * 16 + g;
                afr[mi][0] = As[(kb + tg) * AS_STRIDE + r];
                afr[mi][1] = As[(kb + tg) * AS_STRIDE + r + 8];
                afr[mi][2] = As[(kb + tg + 4) * AS_STRIDE + r];
                afr[mi][3] = As[(kb + tg + 4) * AS_STRIDE + r + 8];
            }
            float bfr[8][2];
#pragma unroll
            for (int ni = 0; ni < 8; ni++) {
                int c = n_base + ni * 8 + g;
                bfr[ni][0] = Bs[(kb + tg) * AS_STRIDE + c];
                bfr[ni][1] = Bs[(kb + tg + 4) * AS_STRIDE + c];
            }
#pragma unroll
            for (int mi = 0; mi < 2; mi++)
#pragma unroll
                for (int ni = 0; ni < 8; ni++)
                    mma_tf32(acc[mi][ni], afr[mi], bfr[ni]);
        }
        __syncthreads();
    }

    // bias per fragment column pair
    float bx[8], by[8];
#pragma unroll
    for (int ni = 0; ni < 8; ni++) {
        int c = n_base + ni * 8 + 2 * tg;
        bx[ni] = bfc1[c];
        by[ni] = bfc1[c + 1];
    }

    // epilogue: stage 64 rows at a time through smem (fp16) for coalesced NHWC stores
    __half* Osm = (__half*)sm;   // [64][OSH]
#pragma unroll
    for (int chunk = 0; chunk < 2; chunk++) {
        if ((warp_m >> 1) == chunk) {
            int rl = (warp_m & 1) * 32;
#pragma unroll
            for (int mi = 0; mi < 2; mi++) {
#pragma unroll
                for (int ni = 0; ni < 8; ni++) {
                    int row = rl + mi * 16 + g;
                    int col = n_base + ni * 8 + 2 * tg;
                    float4 d = acc[mi][ni];
                    *(__half2*)&Osm[row * OSH + col] =
                        __floats2half2_rn(d.x + bx[ni], d.y + by[ni]);
                    *(__half2*)&Osm[(row + 8) * OSH + col] =
                        __floats2half2_rn(d.z + bx[ni], d.w + by[ni]);
                }
            }
        }
        __syncthreads();
#pragma unroll
        for (int i = 0; i < 4; i++) {
            int f   = t + 256 * i;          // 0..1023; 16 x uint4 (8 halves) per row
            int row = f >> 4;
            int h0  = (f & 15) * 8;
            uint4 v = *(const uint4*)&Osm[row * OSH + h0];
            *(uint4*)&O[(size_t)(p0 + chunk * 64 + row) * DLOI + h0] = v;
        }
        __syncthreads();
    }
}

// ---------------- per-line kernel, 256 threads/line ----------------
__global__ __launch_bounds__(256) void line_head(const float* __restrict__ lines,
                                                 const float* __restrict__ c1b,
                                                 const float* __restrict__ c2b,
                                                 const float* __restrict__ c3b,
                                                 const float* __restrict__ wfc2,
                                                 const float* __restrict__ bfc2,
                                                 float* __restrict__ out)
{
    __shared__ float sh1[DLOI * 8];     // bn1+relu, [c][p]
    __shared__ float shv[DLOI * 8];     // raw pooled (residual), [c][p]
    __shared__ float sh2[HALF * 8];
    __shared__ float sh3[HALF * 8];
    __shared__ int4   soff[NPTS0];      // half2-unit pixel offsets for 4 corners
    __shared__ float4 swt[NPTS0];       // bilinear weights
    __shared__ float shred[32];

    int n = blockIdx.x;
    int t = threadIdx.x;
    int b = n / LQ;

    // ---- precompute sample geometry (one sample per thread, t<32) ----
    if (t < NPTS0) {
        const float* ln = lines + (size_t)n * 4;
        float ax = __ldg(ln), ay = __ldg(ln + 1), bx = __ldg(ln + 2), by = __ldg(ln + 3);
        float lam = (float)t * (1.0f / 31.0f);
        float px = ax * lam + bx * (1.0f - lam) - 0.5f;
        float py = ay * lam + by * (1.0f - lam) - 0.5f;
        float px0 = fminf(fmaxf(floorf(px), 0.0f), 255.0f);
        float py0 = fminf(fmaxf(floorf(py), 0.0f), 255.0f);
        float px1 = fminf(px0 + 1.0f, 255.0f);
        float py1 = fminf(py0 + 1.0f, 255.0f);
        int i0 = (int)px0, j0 = (int)py0, i1 = (int)px1, j1 = (int)py1;
        float w00 = (px1 - px) * (py1 - py);
        float w10 = (px - px0) * (py1 - py);
        float w01 = (px1 - px) * (py - py0);
        float w11 = (px - px0) * (py - py0);
        soff[t] = make_int4(((i0 << 8) + j0) << 6, ((i1 << 8) + j0) << 6,
                            ((i0 << 8) + j1) << 6, ((i1 << 8) + j1) << 6);
        swt[t] = make_float4(w00, w10, w01, w11);
    }
    __syncthreads();

    // ---- gather: thread = (channel pair c2 0..63, quarter q 0..3) ----
    {
        int c2 = t & 63, q = t >> 6;
        const __half2* X2 = (const __half2*)g_xh + (size_t)b * HW * 64 + c2;
        int ca = 2 * c2, cb = 2 * c2 + 1;
        float sa = g_bn1s[ca], ta = g_bn1t[ca];
        float sb = g_bn1s[cb], tb = g_bn1t[cb];

        float2 vp[2];
#pragma unroll
        for (int pp = 0; pp < 2; pp++) {
            float2 m = make_float2(-INFINITY, -INFINITY);
#pragma unroll
            for (int kk = 0; kk < 4; kk++) {
                int k = (q * 2 + pp) * 4 + kk;
                int4  o4 = soff[k];
                float4 w4 = swt[k];
                float2 h00 = __half22float2(__ldg(X2 + o4.x));
                float2 h10 = __half22float2(__ldg(X2 + o4.y));
                float2 h01 = __half22float2(__ldg(X2 + o4.z));
                float2 h11 = __half22float2(__ldg(X2 + o4.w));
                float vx = h00.x * w4.x + h10.x * w4.y + h01.x * w4.z + h11.x * w4.w;
                float vy = h00.y * w4.x + h10.y * w4.y + h01.y * w4.z + h11.y * w4.w;
                m.x = fmaxf(m.x, vx);
                m.y = fmaxf(m.y, vy);
            }
            vp[pp] = m;
        }
        int base = q * 2;
        *(float2*)&shv[ca * 8 + base] = make_float2(vp[0].x, vp[1].x);
        *(float2*)&shv[cb * 8 + base] = make_float2(vp[0].y, vp[1].y);
        *(float2*)&sh1[ca * 8 + base] = make_float2(
            fmaxf(vp[0].x * sa + ta, 0.f), fmaxf(vp[1].x * sa + ta, 0.f));
        *(float2*)&sh1[cb * 8 + base] = make_float2(
            fmaxf(vp[0].y * sb + tb, 0.f), fmaxf(vp[1].y * sb + tb, 0.f));
    }
    __syncthreads();

    int o = t & 63, q = t >> 6, pb = q * 2;

    // c1: [64,128] x [128,8]; thread (o, q) does 2 p's
    {
        float a0 = 0.f, a1 = 0.f;
#pragma unroll 8
        for (int c = 0; c < DLOI; c++) {
            float w = g_c1wT[c * HALF + o];
            float2 h = *(const float2*)&sh1[c * 8 + pb];
            a0 += w * h.x; a1 += w * h.y;
        }
        float bias = c1b[o], s2 = g_bn2s[o], t2 = g_bn2t[o];
        *(float2*)&sh2[o * 8 + pb] = make_float2(
            fmaxf((a0 + bias) * s2 + t2, 0.f), fmaxf((a1 + bias) * s2 + t2, 0.f));
    }
    __syncthreads();

    // c2: conv1d k=3 pad=1; thread (o, q) does p = pb, pb+1 (needs h[pb-1..pb+2])
    {
        float a0 = 0.f, a1 = 0.f;
#pragma unroll 4
        for (int i = 0; i < HALF; i++) {
            float2 hm = *(const float2*)&sh2[i * 8 + pb];
            float hl = (pb > 0) ? sh2[i * 8 + pb - 1] : 0.f;
            float hr = (pb < 6) ? sh2[i * 8 + pb + 2] : 0.f;
            float w0 = g_c2wT[(i * 3 + 0) * HALF + o];
            float w1 = g_c2wT[(i * 3 + 1) * HALF + o];
            float w2 = g_c2wT[(i * 3 + 2) * HALF + o];
            a0 += w0 * hl   + w1 * hm.x + w2 * hm.y;
            a1 += w0 * hm.x + w1 * hm.y + w2 * hr;
        }
        float bias = c2b[o], s3 = g_bn3s[o], t3 = g_bn3t[o];
        *(float2*)&sh3[o * 8 + pb] = make_float2(
            fmaxf((a0 + bias) * s3 + t3, 0.f), fmaxf((a1 + bias) * s3 + t3, 0.f));
    }
    __syncthreads();

    // c3 + residual + relu + fc2 partials: thread = (oc 0..127, point-half ph 0..1)
    float part[4];
    {
        int oc = t & 127, ph = t >> 7, p4 = ph * 4;
        float a[4] = {0.f, 0.f, 0.f, 0.f};
#pragma unroll 8
        for (int i = 0; i < HALF; i++) {
            float w = g_c3wT[i * DLOI + oc];
            float4 h = *(const float4*)&sh3[i * 8 + p4];
            a[0] += w * h.x; a[1] += w * h.y; a[2] += w * h.z; a[3] += w * h.w;
        }
        float bias3 = c3b[oc];
        float4 rv = *(const float4*)&shv[oc * 8 + p4];
        float ry0 = fmaxf(rv.x + a[0] + bias3, 0.f);
        float ry1 = fmaxf(rv.y + a[1] + bias3, 0.f);
        float ry2 = fmaxf(rv.z + a[2] + bias3, 0.f);
        float ry3 = fmaxf(rv.w + a[3] + bias3, 0.f);
#pragma unroll
        for (int qq = 0; qq < 4; qq++) {
            float4 wv = *(const float4*)&wfc2[qq * (DLOI * 8) + oc * 8 + p4];
            part[qq] = ry0 * wv.x + ry1 * wv.y + ry2 * wv.z + ry3 * wv.w;
        }
    }
#pragma unroll
    for (int qq = 0; qq < 4; qq++) {
        float v = part[qq];
#pragma unroll
        for (int off = 16; off; off >>= 1) v += __shfl_down_sync(0xffffffffu, v, off);
        part[qq] = v;
    }
    int lane = t & 31, wid = t >> 5;
    if (lane == 0) {
#pragma unroll
        for (int qq = 0; qq < 4; qq++) shred[wid * 4 + qq] = part[qq];
    }
    __syncthreads();
    if (t == 0) {
        float z[4];
#pragma unroll
        for (int qq = 0; qq < 4; qq++) {
            float s = 0.f;
#pragma unroll
            for (int ww = 0; ww < 8; ww++) s += shred[ww * 4 + qq];
            z[qq] = s + bfc2[qq];
        }
        float m = fmaxf(fmaxf(z[0], z[1]), fmaxf(z[2], z[3]));
        float e[4]; float sum = 0.f;
#pragma unroll
        for (int qq = 0; qq < 4; qq++) { e[qq] = expf(z[qq] - m); sum += e[qq]; }
        float inv = 1.0f / sum;
#pragma unroll
        for (int qq = 0; qq < 4; qq++) out[(size_t)n * 4 + qq] = e[qq] * inv;
    }
}

// ---------------- launch ----------------
extern "C" void kernel_launch(void* const* d_in, const int* in_sizes, int n_in,
                              void* d_out, int out_size)
{
    const float* feature = (const float*)d_in[0];
    const float* lines   = (const float*)d_in[1];
    const float* w_fc1   = (const float*)d_in[2];
    const float* b_fc1   = (const float*)d_in[3];
    const float* bn1     = (const float*)d_in[4];
    const float* c1_w    = (const float*)d_in[5];
    const float* c1_b    = (const float*)d_in[6];
    const float* bn2     = (const float*)d_in[7];
    const float* c2_w    = (const float*)d_in[8];
    const float* c2_b    = (const float*)d_in[9];
    const float* bn3     = (const float*)d_in[10];
    const float* c3_w    = (const float*)d_in[11];
    const float* c3_b    = (const float*)d_in[12];
    const float* w_fc2   = (const float*)d_in[13];
    const float* b_fc2   = (const float*)d_in[14];
    float* out = (float*)d_out;

    static int smem_set = 0;
    if (!smem_set) {
        cudaFuncSetAttribute(fc1_gemm_tf32,
                             cudaFuncAttributeMaxDynamicSharedMemorySize, FC1_SMEM);
        smem_set = 1;
    }

    prep_kernel<<<64, 256>>>(w_fc1, bn1, c1_w, bn2, c2_w, bn3, c3_w);

    dim3 grid(HW / 128, BQ);
    fc1_gemm_tf32<<<grid, 256, FC1_SMEM>>>(feature, b_fc1);

    line_head<<<BQ * LQ, 256>>>(lines, c1_b, c2_b, c3_b, w_fc2, b_fc2, out);
}

// round 10
// speedup vs baseline: 1.3216x; 1.3216x over previous
#include <cuda_runtime.h>
#include <cuda_fp16.h>
#include <stdint.h>
#include <math.h>

#define BQ 2
#define LQ 5000
#define CIN 256
#define DLOI 128
#define NPTS0 32
#define NPTS1 8
#define HH 256
#define HALF 64
#define HW (HH*HH)
#define EPSBN 1e-5f

// ---------------- scratch (device globals; no allocation allowed) ----------------
__device__ __half g_xh[BQ * HW * DLOI];        // fc1 output, NHWC, fp16 (33.5 MB)
__device__ float g_wfc1T[CIN * DLOI];          // [k][o], tf32-rounded
__device__ float g_c1wT[DLOI * HALF];          // [c][o]
__device__ float g_c2wT[HALF * 3 * HALF];      // [(i*3+dk)][o]
__device__ float g_c3wT[HALF * DLOI];          // [i][o]
__device__ float g_bn1s[DLOI], g_bn1t[DLOI];
__device__ float g_bn2s[HALF], g_bn2t[HALF];
__device__ float g_bn3s[HALF], g_bn3t[HALF];

__device__ __forceinline__ float to_tf32(float x) {
    uint32_t r;
    asm("cvt.rna.tf32.f32 %0, %1;" : "=r"(r) : "f"(x));
    return __uint_as_float(r);
}

// ---------------- prep: transpose weights, fold BN ----------------
__global__ void prep_kernel(const float* __restrict__ w_fc1,
                            const float* __restrict__ bn1,
                            const float* __restrict__ c1w,
                            const float* __restrict__ bn2,
                            const float* __restrict__ c2w,
                            const float* __restrict__ bn3,
                            const float* __restrict__ c3w)
{
    int t = blockIdx.x * blockDim.x + threadIdx.x;
    int stride = gridDim.x * blockDim.x;
    for (int idx = t; idx < DLOI * CIN; idx += stride) {
        int o = idx / CIN, k = idx % CIN;
        g_wfc1T[k * DLOI + o] = to_tf32(w_fc1[idx]);
    }
    for (int idx = t; idx < HALF * DLOI; idx += stride) {
        int o = idx / DLOI, c = idx % DLOI;
        g_c1wT[c * HALF + o] = c1w[idx];
    }
    for (int idx = t; idx < HALF * HALF * 3; idx += stride) {
        int o = idx / (HALF * 3), r = idx % (HALF * 3);
        g_c2wT[r * HALF + o] = c2w[idx];
    }
    for (int idx = t; idx < DLOI * HALF; idx += stride) {
        int o = idx / HALF, i = idx % HALF;
        g_c3wT[i * DLOI + o] = c3w[idx];
    }
    for (int idx = t; idx < DLOI; idx += stride) {
        float g = bn1[idx], be = bn1[DLOI + idx], mu = bn1[2*DLOI + idx], va = bn1[3*DLOI + idx];
        float s = g * rsqrtf(va + EPSBN);
        g_bn1s[idx] = s; g_bn1t[idx] = be - mu * s;
    }
    for (int idx = t; idx < HALF; idx += stride) {
        float g = bn2[idx], be = bn2[HALF + idx], mu = bn2[2*HALF + idx], va = bn2[3*HALF + idx];
        float s = g * rsqrtf(va + EPSBN);
        g_bn2s[idx] = s; g_bn2t[idx] = be - mu * s;
        float g3 = bn3[idx], be3 = bn3[HALF + idx], mu3 = bn3[2*HALF + idx], va3 = bn3[3*HALF + idx];
        float s3 = g3 * rsqrtf(va3 + EPSBN);
        g_bn3s[idx] = s3; g_bn3t[idx] = be3 - mu3 * s3;
    }
}

// ---------------- fc1 GEMM: BM=256 x BN=128, tf32 mma.sync + cp.async ----------
#define KT 32                   // k per smem stage
#define ASTR 260                // A stage stride (256 + 4 pad)
#define BSTR 132                // B stage stride (128 + 4 pad)
#define OSH 136                 // epilogue half staging stride (halves)
#define STAGE_FLOATS (KT * ASTR + KT * BSTR)
#define FC1_SMEM (2 * STAGE_FLOATS * 4)

__device__ __forceinline__ void cp_async16(void* smem_ptr, const void* gmem_ptr) {
    uint32_t s = (uint32_t)__cvta_generic_to_shared(smem_ptr);
    asm volatile("cp.async.cg.shared.global [%0], [%1], 16;\n" :: "r"(s), "l"(gmem_ptr));
}

__device__ __forceinline__ void mma_tf32(float4& d, const float* a, const float* b) {
    asm volatile(
        "mma.sync.aligned.m16n8k8.row.col.f32.tf32.tf32.f32 "
        "{%0,%1,%2,%3}, {%4,%5,%6,%7}, {%8,%9}, {%0,%1,%2,%3};\n"
        : "+f"(d.x), "+f"(d.y), "+f"(d.z), "+f"(d.w)
        : "r"(__float_as_uint(a[0])), "r"(__float_as_uint(a[1])),
          "r"(__float_as_uint(a[2])), "r"(__float_as_uint(a[3])),
          "r"(__float_as_uint(b[0])), "r"(__float_as_uint(b[1])));
}

__global__ __launch_bounds__(256) void fc1_gemm_tf32(const float* __restrict__ feat,
                                                     const float* __restrict__ bfc1)
{
    extern __shared__ float sm[];

    int b  = blockIdx.y;
    int p0 = blockIdx.x * 256;
    const float* A = feat + (size_t)b * CIN * HW;
    __half* O = g_xh + (size_t)b * HW * DLOI;

    int t    = threadIdx.x;
    int w    = t >> 5;
    int lane = t & 31;
    int g    = lane >> 2;        // 0..7
    int tg   = lane & 3;         // 0..3
    int warp_m = w & 3;          // 0..3  -> rows warp_m*64 .. +63
    int warp_n = w >> 2;         // 0..1  -> cols warp_n*64 .. +63
    int m_base = warp_m * 64;
    int n_base = warp_n * 64;

    float4 acc[4][8];
#pragma unroll
    for (int mi = 0; mi < 4; mi++)
#pragma unroll
        for (int ni = 0; ni < 8; ni++) acc[mi][ni] = make_float4(0.f, 0.f, 0.f, 0.f);

    auto issue_stage = [&](int s) {
        float* As = sm + (s & 1) * STAGE_FLOATS;
        float* Bs = As + KT * ASTR;
        int k0 = s * KT;
        // A: 32 k-rows x 256 p -> 2048 float4, 8 per thread
#pragma unroll
        for (int i = 0; i < 8; i++) {
            int f  = t + 256 * i;
            int kk = f >> 6;
            int pm = (f & 63) * 4;
            cp_async16(&As[kk * ASTR + pm], &A[(size_t)(k0 + kk) * HW + p0 + pm]);
        }
        // B: 32 k-rows x 128 o -> 1024 float4, 4 per thread
#pragma unroll
        for (int i = 0; i < 4; i++) {
            int f  = t + 256 * i;
            int kk = f >> 5;
            int pm = (f & 31) * 4;
            cp_async16(&Bs[kk * BSTR + pm], &g_wfc1T[(k0 + kk) * DLOI + pm]);
        }
        asm volatile("cp.async.commit_group;\n");
    };

    issue_stage(0);

    const int NS = CIN / KT;     // 8
    for (int s = 0; s < NS; s++) {
        if (s + 1 < NS) {
            issue_stage(s + 1);
            asm volatile("cp.async.wait_group 1;\n");
        } else {
            asm volatile("cp.async.wait_group 0;\n");
        }
        __syncthreads();

        float* As = sm + (s & 1) * STAGE_FLOATS;
        float* Bs = As + KT * ASTR;

#pragma unroll
        for (int ks = 0; ks < KT / 8; ks++) {
            int kb = ks * 8;
            float afr[4][4];
#pragma unroll
            for (int mi = 0; mi < 4; mi++) {
                int r = m_base + mi * 16 + g;
                afr[mi][0] = As[(kb + tg) * ASTR + r];
                afr[mi][1] = As[(kb + tg) * ASTR + r + 8];
                afr[mi][2] = As[(kb + tg + 4) * ASTR + r];
                afr[mi][3] = As[(kb + tg + 4) * ASTR + r + 8];
            }
            float bfr[8][2];
#pragma unroll
            for (int ni = 0; ni < 8; ni++) {
                int c = n_base + ni * 8 + g;
                bfr[ni][0] = Bs[(kb + tg) * BSTR + c];
                bfr[ni][1] = Bs[(kb + tg + 4) * BSTR + c];
            }
#pragma unroll
            for (int mi = 0; mi < 4; mi++)
#pragma unroll
                for (int ni = 0; ni < 8; ni++)
                    mma_tf32(acc[mi][ni], afr[mi], bfr[ni]);
        }
        __syncthreads();
    }

    // bias per fragment column pair
    float bx[8], by[8];
#pragma unroll
    for (int ni = 0; ni < 8; ni++) {
        int c = n_base + ni * 8 + 2 * tg;
        bx[ni] = bfc1[c];
        by[ni] = bfc1[c + 1];
    }

    // epilogue: 4 chunks of 64 rows staged through smem (fp16), coalesced stores
    __half* Osm = (__half*)sm;   // [64][OSH]
#pragma unroll
    for (int chunk = 0; chunk < 4; chunk++) {
        if (warp_m == chunk) {
#pragma unroll
            for (int mi = 0; mi < 4; mi++) {
#pragma unroll
                for (int ni = 0; ni < 8; ni++) {
                    int row = mi * 16 + g;
                    int col = n_base + ni * 8 + 2 * tg;
                    float4 d = acc[mi][ni];
                    *(__half2*)&Osm[row * OSH + col] =
                        __floats2half2_rn(d.x + bx[ni], d.y + by[ni]);
                    *(__half2*)&Osm[(row + 8) * OSH + col] =
                        __floats2half2_rn(d.z + bx[ni], d.w + by[ni]);
                }
            }
        }
        __syncthreads();
#pragma unroll
        for (int i = 0; i < 4; i++) {
            int f   = t + 256 * i;          // 0..1023; 16 x uint4 per 128-half row
            int row = f >> 4;
            int h0  = (f & 15) * 8;
            uint4 v = *(const uint4*)&Osm[row * OSH + h0];
            *(uint4*)&O[(size_t)(p0 + chunk * 64 + row) * DLOI + h0] = v;
        }
        __syncthreads();
    }
}

// ---------------- per-line kernel (R7 proven version, 128 threads) ----------------
__global__ __launch_bounds__(128) void line_head(const float* __restrict__ lines,
                                                 const float* __restrict__ c1b,
                                                 const float* __restrict__ c2b,
                                                 const float* __restrict__ c3b,
                                                 const float* __restrict__ wfc2,
                                                 const float* __restrict__ bfc2,
                                                 float* __restrict__ out)
{
    __shared__ float sh1[DLOI * 8];     // bn1+relu, [c][p]
    __shared__ float shv[DLOI * 8];     // raw pooled (residual), [c][p]
    __shared__ float sh2[HALF * 8];
    __shared__ float sh3[HALF * 8];
    __shared__ int4   soff[NPTS0];      // half2-unit pixel offsets for 4 corners
    __shared__ float4 swt[NPTS0];       // bilinear weights
    __shared__ float shred[16];

    int n = blockIdx.x;
    int t = threadIdx.x;
    int b = n / LQ;

    // ---- precompute sample geometry (one sample per thread, t<32) ----
    if (t < NPTS0) {
        const float* ln = lines + (size_t)n * 4;
        float ax = __ldg(ln), ay = __ldg(ln + 1), bx = __ldg(ln + 2), by = __ldg(ln + 3);
        float lam = (float)t * (1.0f / 31.0f);
        float px = ax * lam + bx * (1.0f - lam) - 0.5f;
        float py = ay * lam + by * (1.0f - lam) - 0.5f;
        float px0 = fminf(fmaxf(floorf(px), 0.0f), 255.0f);
        float py0 = fminf(fmaxf(floorf(py), 0.0f), 255.0f);
        float px1 = fminf(px0 + 1.0f, 255.0f);
        float py1 = fminf(py0 + 1.0f, 255.0f);
        int i0 = (int)px0, j0 = (int)py0, i1 = (int)px1, j1 = (int)py1;
        float w00 = (px1 - px) * (py1 - py);
        float w10 = (px - px0) * (py1 - py);
        float w01 = (px1 - px) * (py - py0);
        float w11 = (px - px0) * (py - py0);
        soff[t] = make_int4(((i0 << 8) + j0) << 6, ((i1 << 8) + j0) << 6,
                            ((i0 << 8) + j1) << 6, ((i1 << 8) + j1) << 6);
        swt[t] = make_float4(w00, w10, w01, w11);
    }
    __syncthreads();

    // ---- gather: thread = (channel pair c2, point half ph) ----
    int c2 = t & 63, ph = t >> 6;
    const __half2* X2 = (const __half2*)g_xh + (size_t)b * HW * 64 + c2;

    float2 vp[4];
#pragma unroll
    for (int pp = 0; pp < 4; pp++) {
        float2 m = make_float2(-INFINITY, -INFINITY);
#pragma unroll
        for (int kk = 0; kk < 4; kk++) {
            int k = (ph * 4 + pp) * 4 + kk;
            int4  o4 = soff[k];
            float4 w4 = swt[k];
            float2 h00 = __half22float2(__ldg(X2 + o4.x));
            float2 h10 = __half22float2(__ldg(X2 + o4.y));
            float2 h01 = __half22float2(__ldg(X2 + o4.z));
            float2 h11 = __half22float2(__ldg(X2 + o4.w));
            float vx = h00.x * w4.x + h10.x * w4.y + h01.x * w4.z + h11.x * w4.w;
            float vy = h00.y * w4.x + h10.y * w4.y + h01.y * w4.z + h11.y * w4.w;
            m.x = fmaxf(m.x, vx);
            m.y = fmaxf(m.y, vy);
        }
        vp[pp] = m;
    }

    // ---- store residual + bn1+relu to smem ([c][p], float4 along p) ----
    {
        int ca = 2 * c2, cb = 2 * c2 + 1;
        float sa = g_bn1s[ca], ta = g_bn1t[ca];
        float sb = g_bn1s[cb], tb = g_bn1t[cb];
        int base = ph * 4;
        *(float4*)&shv[ca * 8 + base] = make_float4(vp[0].x, vp[1].x, vp[2].x, vp[3].x);
        *(float4*)&shv[cb * 8 + base] = make_float4(vp[0].y, vp[1].y, vp[2].y, vp[3].y);
        *(float4*)&sh1[ca * 8 + base] = make_float4(
            fmaxf(vp[0].x * sa + ta, 0.f), fmaxf(vp[1].x * sa + ta, 0.f),
            fmaxf(vp[2].x * sa + ta, 0.f), fmaxf(vp[3].x * sa + ta, 0.f));
        *(float4*)&sh1[cb * 8 + base] = make_float4(
            fmaxf(vp[0].y * sb + tb, 0.f), fmaxf(vp[1].y * sb + tb, 0.f),
            fmaxf(vp[2].y * sb + tb, 0.f), fmaxf(vp[3].y * sb + tb, 0.f));
    }
    __syncthreads();

    int o = t & 63, half = t >> 6, pb = half * 4;

    // c1: [64,128] x [128,8] -> [64,8]; thread (o, half) does 4 p's
    float acc1[4] = {0.f, 0.f, 0.f, 0.f};
#pragma unroll 4
    for (int c = 0; c < DLOI; c++) {
        float w = g_c1wT[c * HALF + o];
        float4 h = *(const float4*)&sh1[c * 8 + pb];
        acc1[0] += w * h.x; acc1[1] += w * h.y; acc1[2] += w * h.z; acc1[3] += w * h.w;
    }
    {
        float bias = c1b[o], s2 = g_bn2s[o], t2 = g_bn2t[o];
#pragma unroll
        for (int j = 0; j < 4; j++)
            sh2[o * 8 + pb + j] = fmaxf((acc1[j] + bias) * s2 + t2, 0.0f);
    }
    __syncthreads();

    // c2: conv1d k=3 pad=1 over p, [64,64,3]
    float acc2[4] = {0.f, 0.f, 0.f, 0.f};
#pragma unroll 2
    for (int i = 0; i < HALF; i++) {
        float4 r0 = *(const float4*)&sh2[i * 8];
        float4 r1 = *(const float4*)&sh2[i * 8 + 4];
        float h[6];
        if (half == 0) { h[0] = 0.f;  h[1] = r0.x; h[2] = r0.y; h[3] = r0.z; h[4] = r0.w; h[5] = r1.x; }
        else           { h[0] = r0.w; h[1] = r1.x; h[2] = r1.y; h[3] = r1.z; h[4] = r1.w; h[5] = 0.f;  }
        float w0 = g_c2wT[(i * 3 + 0) * HALF + o];
        float w1 = g_c2wT[(i * 3 + 1) * HALF + o];
        float w2 = g_c2wT[(i * 3 + 2) * HALF + o];
#pragma unroll
        for (int j = 0; j < 4; j++)
            acc2[j] += w0 * h[j] + w1 * h[j + 1] + w2 * h[j + 2];
    }
    {
        float bias = c2b[o], s3 = g_bn3s[o], t3 = g_bn3t[o];
#pragma unroll
        for (int j = 0; j < 4; j++)
            sh3[o * 8 + pb + j] = fmaxf((acc2[j] + bias) * s3 + t3, 0.0f);
    }
    __syncthreads();

    // c3: [128,64] x [64,8] -> [128,8]; thread t = output channel, all 8 p's
    float acc3[8] = {0.f,0.f,0.f,0.f,0.f,0.f,0.f,0.f};
#pragma unroll 4
    for (int i = 0; i < HALF; i++) {
        float w = g_c3wT[i * DLOI + t];
        float4 r0 = *(const float4*)&sh3[i * 8];
        float4 r1 = *(const float4*)&sh3[i * 8 + 4];
        acc3[0] += w * r0.x; acc3[1] += w * r0.y; acc3[2] += w * r0.z; acc3[3] += w * r0.w;
        acc3[4] += w * r1.x; acc3[5] += w * r1.y; acc3[6] += w * r1.z; acc3[7] += w * r1.w;
    }
    float bias3 = c3b[t];
    float4 rv0 = *(const float4*)&shv[t * 8];
    float4 rv1 = *(const float4*)&shv[t * 8 + 4];
    float ry[8];
    ry[0] = fmaxf(rv0.x + acc3[0] + bias3, 0.f);
    ry[1] = fmaxf(rv0.y + acc3[1] + bias3, 0.f);
    ry[2] = fmaxf(rv0.z + acc3[2] + bias3, 0.f);
    ry[3] = fmaxf(rv0.w + acc3[3] + bias3, 0.f);
    ry[4] = fmaxf(rv1.x + acc3[4] + bias3, 0.f);
    ry[5] = fmaxf(rv1.y + acc3[5] + bias3, 0.f);
    ry[6] = fmaxf(rv1.z + acc3[6] + bias3, 0.f);
    ry[7] = fmaxf(rv1.w + acc3[7] + bias3, 0.f);

    // fc2 partials: flat index = t*8 + p
    float part[4];
#pragma unroll
    for (int q = 0; q < 4; q++) {
        const float* wq = wfc2 + q * (DLOI * 8) + t * 8;
        float4 w0 = *(const float4*)wq;
        float4 w1 = *(const float4*)(wq + 4);
        part[q] = ry[0] * w0.x + ry[1] * w0.y + ry[2] * w0.z + ry[3] * w0.w
                + ry[4] * w1.x + ry[5] * w1.y + ry[6] * w1.z + ry[7] * w1.w;
    }
#pragma unroll
    for (int q = 0; q < 4; q++) {
        float v = part[q];
#pragma unroll
        for (int off = 16; off; off >>= 1) v += __shfl_down_sync(0xffffffffu, v, off);
        part[q] = v;
    }
    int lane = t & 31, wid = t >> 5;
    if (lane == 0) {
#pragma unroll
        for (int q = 0; q < 4; q++) shred[wid * 4 + q] = part[q];
    }
    __syncthreads();
    if (t == 0) {
        float z[4];
#pragma unroll
        for (int q = 0; q < 4; q++)
            z[q] = shred[q] + shred[4 + q] + shred[8 + q] + shred[12 + q] + bfc2[q];
        float m = fmaxf(fmaxf(z[0], z[1]), fmaxf(z[2], z[3]));
        float e[4]; float sum = 0.f;
#pragma unroll
        for (int q = 0; q < 4; q++) { e[q] = expf(z[q] - m); sum += e[q]; }
        float inv = 1.0f / sum;
#pragma unroll
        for (int q = 0; q < 4; q++) out[(size_t)n * 4 + q] = e[q] * inv;
    }
}

// ---------------- launch ----------------
extern "C" void kernel_launch(void* const* d_in, const int* in_sizes, int n_in,
                              void* d_out, int out_size)
{
    const float* feature = (const float*)d_in[0];
    const float* lines   = (const float*)d_in[1];
    const float* w_fc1   = (const float*)d_in[2];
    const float* b_fc1   = (const float*)d_in[3];
    const float* bn1     = (const float*)d_in[4];
    const float* c1_w    = (const float*)d_in[5];
    const float* c1_b    = (const float*)d_in[6];
    const float* bn2     = (const float*)d_in[7];
    const float* c2_w    = (const float*)d_in[8];
    const float* c2_b    = (const float*)d_in[9];
    const float* bn3     = (const float*)d_in[10];
    const float* c3_w    = (const float*)d_in[11];
    const float* c3_b    = (const float*)d_in[12];
    const float* w_fc2   = (const float*)d_in[13];
    const float* b_fc2   = (const float*)d_in[14];
    float* out = (float*)d_out;

    static int smem_set = 0;
    if (!smem_set) {
        cudaFuncSetAttribute(fc1_gemm_tf32,
                             cudaFuncAttributeMaxDynamicSharedMemorySize, FC1_SMEM);
        smem_set = 1;
    }

    prep_kernel<<<64, 256>>>(w_fc1, bn1, c1_w, bn2, c2_w, bn3, c3_w);

    dim3 grid(HW / 256, BQ);
    fc1_gemm_tf32<<<grid, 256, FC1_SMEM>>>(feature, b_fc1);

    line_head<<<BQ * LQ, 128>>>(lines, c1_b, c2_b, c3_b, w_fc2, b_fc2, out);
}

// round 11
// speedup vs baseline: 1.9167x; 1.4503x over previous
#include <cuda_runtime.h>
#include <cuda_fp16.h>
#include <stdint.h>
#include <math.h>

#define BQ 2
#define LQ 5000
#define NL (BQ*LQ)
#define RROWS (NL*8)
#define CIN 256
#define DLOI 128
#define NPTS0 32
#define NPTS1 8
#define HH 256
#define HALF 64
#define HW (HH*HH)
#define EPSBN 1e-5f

// ---------------- scratch (device globals; no allocation allowed) ----------------
__device__ __half g_xh[BQ * HW * DLOI];        // fc1 output, NHWC, fp16 (33.5 MB)
__device__ float g_wfc1T[CIN * DLOI];          // [k][o], tf32-rounded
__device__ float g_c1wT[DLOI * HALF];          // [k=c][n=o], tf32
__device__ float g_c2wG[192 * HALF];           // [dk*64+i][o], tf32
__device__ float g_c3wT[HALF * DLOI];          // [k=i][n=o], tf32
__device__ float g_bn1s[DLOI], g_bn1t[DLOI];
__device__ float g_bn2s[HALF], g_bn2t[HALF];
__device__ float g_bn3s[HALF], g_bn3t[HALF];
// line pipeline buffers
__device__ float g_h1[RROWS * DLOI];           // bn1+relu(xp), tf32 (41 MB)
__device__ float g_xp[RROWS * DLOI];           // raw pooled residual (41 MB)
__device__ float g_h2p[NL * 10 * HALF];        // padded rows; pads stay zero (25.6 MB)
__device__ float g_h3[RROWS * HALF];           // (20.5 MB)
__device__ float g_y[NL * DLOI * NPTS1];       // relu(xp + c3out), flat [n][c*8+p] (41 MB)

__device__ __forceinline__ float to_tf32(float x) {
    uint32_t r;
    asm("cvt.rna.tf32.f32 %0, %1;" : "=r"(r) : "f"(x));
    return __uint_as_float(r);
}

// ---------------- prep: transpose weights (tf32), fold BN ----------------
__global__ void prep_kernel(const float* __restrict__ w_fc1,
                            const float* __restrict__ bn1,
                            const float* __restrict__ c1w,
                            const float* __restrict__ bn2,
                            const float* __restrict__ c2w,
                            const float* __restrict__ bn3,
                            const float* __restrict__ c3w)
{
    int t = blockIdx.x * blockDim.x + threadIdx.x;
    int stride = gridDim.x * blockDim.x;
    for (int idx = t; idx < DLOI * CIN; idx += stride) {
        int o = idx / CIN, k = idx % CIN;
        g_wfc1T[k * DLOI + o] = to_tf32(w_fc1[idx]);
    }
    for (int idx = t; idx < HALF * DLOI; idx += stride) {
        int o = idx / DLOI, c = idx % DLOI;
        g_c1wT[c * HALF + o] = to_tf32(c1w[idx]);
    }
    for (int idx = t; idx < HALF * HALF * 3; idx += stride) {
        // c2w: [o][i][dk] -> g_c2wG[(dk*64+i)][o]
        int o = idx / (HALF * 3), rem = idx % (HALF * 3);
        int i = rem / 3, dk = rem % 3;
        g_c2wG[(dk * HALF + i) * HALF + o] = to_tf32(c2w[idx]);
    }
    for (int idx = t; idx < DLOI * HALF; idx += stride) {
        int o = idx / HALF, i = idx % HALF;
        g_c3wT[i * DLOI + o] = to_tf32(c3w[idx]);
    }
    for (int idx = t; idx < DLOI; idx += stride) {
        float g = bn1[idx], be = bn1[DLOI + idx], mu = bn1[2*DLOI + idx], va = bn1[3*DLOI + idx];
        float s = g * rsqrtf(va + EPSBN);
        g_bn1s[idx] = s; g_bn1t[idx] = be - mu * s;
    }
    for (int idx = t; idx < HALF; idx += stride) {
        float g = bn2[idx], be = bn2[HALF + idx], mu = bn2[2*HALF + idx], va = bn2[3*HALF + idx];
        float s = g * rsqrtf(va + EPSBN);
        g_bn2s[idx] = s; g_bn2t[idx] = be - mu * s;
        float g3 = bn3[idx], be3 = bn3[HALF + idx], mu3 = bn3[2*HALF + idx], va3 = bn3[3*HALF + idx];
        float s3 = g3 * rsqrtf(va3 + EPSBN);
        g_bn3s[idx] = s3; g_bn3t[idx] = be3 - mu3 * s3;
    }
}

// ---------------- shared MMA helpers ----------------
__device__ __forceinline__ void cp_async16(void* smem_ptr, const void* gmem_ptr) {
    uint32_t s = (uint32_t)__cvta_generic_to_shared(smem_ptr);
    asm volatile("cp.async.cg.shared.global [%0], [%1], 16;\n" :: "r"(s), "l"(gmem_ptr));
}

__device__ __forceinline__ void mma_tf32(float4& d, const float* a, const float* b) {
    asm volatile(
        "mma.sync.aligned.m16n8k8.row.col.f32.tf32.tf32.f32 "
        "{%0,%1,%2,%3}, {%4,%5,%6,%7}, {%8,%9}, {%0,%1,%2,%3};\n"
        : "+f"(d.x), "+f"(d.y), "+f"(d.z), "+f"(d.w)
        : "r"(__float_as_uint(a[0])), "r"(__float_as_uint(a[1])),
          "r"(__float_as_uint(a[2])), "r"(__float_as_uint(a[3])),
          "r"(__float_as_uint(b[0])), "r"(__float_as_uint(b[1])));
}

// ---------------- fc1 GEMM: BM=256 x BN=128, tf32 mma.sync + cp.async ----------
#define KT 32
#define ASTR 260
#define BSTR 132
#define OSH 136
#define STAGE_FLOATS (KT * ASTR + KT * BSTR)
#define FC1_SMEM (2 * STAGE_FLOATS * 4)

__global__ __launch_bounds__(256) void fc1_gemm_tf32(const float* __restrict__ feat,
                                                     const float* __restrict__ bfc1)
{
    extern __shared__ float sm[];

    int b  = blockIdx.y;
    int p0 = blockIdx.x * 256;
    const float* A = feat + (size_t)b * CIN * HW;
    __half* O = g_xh + (size_t)b * HW * DLOI;

    int t    = threadIdx.x;
    int w    = t >> 5;
    int lane = t & 31;
    int g    = lane >> 2;
    int tg   = lane & 3;
    int warp_m = w & 3;
    int warp_n = w >> 2;
    int m_base = warp_m * 64;
    int n_base = warp_n * 64;

    float4 acc[4][8];
#pragma unroll
    for (int mi = 0; mi < 4; mi++)
#pragma unroll
        for (int ni = 0; ni < 8; ni++) acc[mi][ni] = make_float4(0.f, 0.f, 0.f, 0.f);

    auto issue_stage = [&](int s) {
        float* As = sm + (s & 1) * STAGE_FLOATS;
        float* Bs = As + KT * ASTR;
        int k0 = s * KT;
#pragma unroll
        for (int i = 0; i < 8; i++) {
            int f  = t + 256 * i;
            int kk = f >> 6;
            int pm = (f & 63) * 4;
            cp_async16(&As[kk * ASTR + pm], &A[(size_t)(k0 + kk) * HW + p0 + pm]);
        }
#pragma unroll
        for (int i = 0; i < 4; i++) {
            int f  = t + 256 * i;
            int kk = f >> 5;
            int pm = (f & 31) * 4;
            cp_async16(&Bs[kk * BSTR + pm], &g_wfc1T[(k0 + kk) * DLOI + pm]);
        }
        asm volatile("cp.async.commit_group;\n");
    };

    issue_stage(0);

    const int NS = CIN / KT;
    for (int s = 0; s < NS; s++) {
        if (s + 1 < NS) {
            issue_stage(s + 1);
            asm volatile("cp.async.wait_group 1;\n");
        } else {
            asm volatile("cp.async.wait_group 0;\n");
        }
        __syncthreads();

        float* As = sm + (s & 1) * STAGE_FLOATS;
        float* Bs = As + KT * ASTR;

#pragma unroll
        for (int ks = 0; ks < KT / 8; ks++) {
            int kb = ks * 8;
            float afr[4][4];
#pragma unroll
            for (int mi = 0; mi < 4; mi++) {
                int r = m_base + mi * 16 + g;
                afr[mi][0] = As[(kb + tg) * ASTR + r];
                afr[mi][1] = As[(kb + tg) * ASTR + r + 8];
                afr[mi][2] = As[(kb + tg + 4) * ASTR + r];
                afr[mi][3] = As[(kb + tg + 4) * ASTR + r + 8];
            }
            float bfr[8][2];
#pragma unroll
            for (int ni = 0; ni < 8; ni++) {
                int c = n_base + ni * 8 + g;
                bfr[ni][0] = Bs[(kb + tg) * BSTR + c];
                bfr[ni][1] = Bs[(kb + tg + 4) * BSTR + c];
            }
#pragma unroll
            for (int mi = 0; mi < 4; mi++)
#pragma unroll
                for (int ni = 0; ni < 8; ni++)
                    mma_tf32(acc[mi][ni], afr[mi], bfr[ni]);
        }
        __syncthreads();
    }

    float bx[8], by[8];
#pragma unroll
    for (int ni = 0; ni < 8; ni++) {
        int c = n_base + ni * 8 + 2 * tg;
        bx[ni] = bfc1[c];
        by[ni] = bfc1[c + 1];
    }

    __half* Osm = (__half*)sm;
#pragma unroll
    for (int chunk = 0; chunk < 4; chunk++) {
        if (warp_m == chunk) {
#pragma unroll
            for (int mi = 0; mi < 4; mi++) {
#pragma unroll
                for (int ni = 0; ni < 8; ni++) {
                    int row = mi * 16 + g;
                    int col = n_base + ni * 8 + 2 * tg;
                    float4 d = acc[mi][ni];
                    *(__half2*)&Osm[row * OSH + col] =
                        __floats2half2_rn(d.x + bx[ni], d.y + by[ni]);
                    *(__half2*)&Osm[(row + 8) * OSH + col] =
                        __floats2half2_rn(d.z + bx[ni], d.w + by[ni]);
                }
            }
        }
        __syncthreads();
#pragma unroll
        for (int i = 0; i < 4; i++) {
            int f   = t + 256 * i;
            int row = f >> 4;
            int h0  = (f & 15) * 8;
            uint4 v = *(const uint4*)&Osm[row * OSH + h0];
            *(uint4*)&O[(size_t)(p0 + chunk * 64 + row) * DLOI + h0] = v;
        }
        __syncthreads();
    }
}

// ---------------- line_gather: geometry + bilinear + maxpool -> g_h1, g_xp ----
__global__ __launch_bounds__(128) void line_gather(const float* __restrict__ lines)
{
    __shared__ int4   soff[NPTS0];
    __shared__ float4 swt[NPTS0];

    int n = blockIdx.x;
    int t = threadIdx.x;
    int b = n / LQ;

    if (t < NPTS0) {
        const float* ln = lines + (size_t)n * 4;
        float ax = __ldg(ln), ay = __ldg(ln + 1), bx = __ldg(ln + 2), by = __ldg(ln + 3);
        float lam = (float)t * (1.0f / 31.0f);
        float px = ax * lam + bx * (1.0f - lam) - 0.5f;
        float py = ay * lam + by * (1.0f - lam) - 0.5f;
        float px0 = fminf(fmaxf(floorf(px), 0.0f), 255.0f);
        float py0 = fminf(fmaxf(floorf(py), 0.0f), 255.0f);
        float px1 = fminf(px0 + 1.0f, 255.0f);
        float py1 = fminf(py0 + 1.0f, 255.0f);
        int i0 = (int)px0, j0 = (int)py0, i1 = (int)px1, j1 = (int)py1;
        float w00 = (px1 - px) * (py1 - py);
        float w10 = (px - px0) * (py1 - py);
        float w01 = (px1 - px) * (py - py0);
        float w11 = (px - px0) * (py - py0);
        soff[t] = make_int4(((i0 << 8) + j0) << 6, ((i1 << 8) + j0) << 6,
                            ((i0 << 8) + j1) << 6, ((i1 << 8) + j1) << 6);
        swt[t] = make_float4(w00, w10, w01, w11);
    }
    __syncthreads();

    int c2 = t & 63, ph = t >> 6;
    const __half2* X2 = (const __half2*)g_xh + (size_t)b * HW * 64 + c2;

    int ca = 2 * c2, cb = 2 * c2 + 1;
    float sa = g_bn1s[ca], ta = g_bn1t[ca];
    float sb = g_bn1s[cb], tb = g_bn1t[cb];

#pragma unroll
    for (int pp = 0; pp < 4; pp++) {
        float2 m = make_float2(-INFINITY, -INFINITY);
#pragma unroll
        for (int kk = 0; kk < 4; kk++) {
            int k = (ph * 4 + pp) * 4 + kk;
            int4  o4 = soff[k];
            float4 w4 = swt[k];
            float2 h00 = __half22float2(__ldg(X2 + o4.x));
            float2 h10 = __half22float2(__ldg(X2 + o4.y));
            float2 h01 = __half22float2(__ldg(X2 + o4.z));
            float2 h11 = __half22float2(__ldg(X2 + o4.w));
            float vx = h00.x * w4.x + h10.x * w4.y + h01.x * w4.z + h11.x * w4.w;
            float vy = h00.y * w4.x + h10.y * w4.y + h01.y * w4.z + h11.y * w4.w;
            m.x = fmaxf(m.x, vx);
            m.y = fmaxf(m.y, vy);
        }
        int p = ph * 4 + pp;
        size_t base = ((size_t)n * 8 + p) * DLOI + ca;
        *(float2*)&g_xp[base] = m;
        *(float2*)&g_h1[base] = make_float2(
            to_tf32(fmaxf(m.x * sa + ta, 0.f)),
            to_tf32(fmaxf(m.y * sb + tb, 0.f)));
    }
}

// ---------------- c1 GEMM: [80000,128] x [128,64] -> h2p (padded, bn2+relu) ----
#define C1_AS 132
#define C1_BS 68
#define C1_SMEM ((128*C1_AS + 128*C1_BS) * 4)

__global__ __launch_bounds__(256) void c1_gemm(const float* __restrict__ c1b)
{
    extern __shared__ float sm[];
    float* Asm = sm;                 // [128][C1_AS]  (m x k)
    float* Bsm = sm + 128 * C1_AS;   // [128][C1_BS]  (k x n)

    int r0 = blockIdx.x * 128;
    int t = threadIdx.x;
    int w = t >> 5, lane = t & 31, g = lane >> 2, tg = lane & 3;
    int m_base = (w & 3) * 32;
    int n_base = (w >> 2) * 32;

#pragma unroll
    for (int i = 0; i < 16; i++) {
        int f = t + 256 * i;             // 4096 float4: 128 rows x 32
        int row = f >> 5, c4 = (f & 31) * 4;
        cp_async16(&Asm[row * C1_AS + c4], &g_h1[(size_t)(r0 + row) * DLOI + c4]);
    }
#pragma unroll
    for (int i = 0; i < 8; i++) {
        int f = t + 256 * i;             // 2048 float4: 128 rows x 16
        int row = f >> 4, c4 = (f & 15) * 4;
        cp_async16(&Bsm[row * C1_BS + c4], &g_c1wT[row * HALF + c4]);
    }
    asm volatile("cp.async.commit_group;\ncp.async.wait_group 0;\n");
    __syncthreads();

    float4 acc[2][4];
#pragma unroll
    for (int mi = 0; mi < 2; mi++)
#pragma unroll
        for (int ni = 0; ni < 4; ni++) acc[mi][ni] = make_float4(0.f,0.f,0.f,0.f);

#pragma unroll
    for (int ks = 0; ks < 16; ks++) {
        int kb = ks * 8;
        float afr[2][4];
#pragma unroll
        for (int mi = 0; mi < 2; mi++) {
            int r = m_base + mi * 16 + g;
            afr[mi][0] = Asm[r * C1_AS + kb + tg];
            afr[mi][1] = Asm[(r + 8) * C1_AS + kb + tg];
            afr[mi][2] = Asm[r * C1_AS + kb + tg + 4];
            afr[mi][3] = Asm[(r + 8) * C1_AS + kb + tg + 4];
        }
        float bfr[4][2];
#pragma unroll
        for (int ni = 0; ni < 4; ni++) {
            int c = n_base + ni * 8 + g;
            bfr[ni][0] = Bsm[(kb + tg) * C1_BS + c];
            bfr[ni][1] = Bsm[(kb + tg + 4) * C1_BS + c];
        }
#pragma unroll
        for (int mi = 0; mi < 2; mi++)
#pragma unroll
            for (int ni = 0; ni < 4; ni++)
                mma_tf32(acc[mi][ni], afr[mi], bfr[ni]);
    }

#pragma unroll
    for (int ni = 0; ni < 4; ni++) {
        int o0 = n_base + ni * 8 + 2 * tg, o1 = o0 + 1;
        float bia0 = __ldg(&c1b[o0]) , bia1 = __ldg(&c1b[o1]);
        float s0 = g_bn2s[o0], t0 = g_bn2t[o0];
        float s1 = g_bn2s[o1], t1 = g_bn2t[o1];
#pragma unroll
        for (int mi = 0; mi < 2; mi++) {
            float4 d = acc[mi][ni];
            int r = r0 + m_base + mi * 16 + g;
            int q = (r >> 3) * 10 + (r & 7) + 1;
            g_h2p[q * HALF + o0] = to_tf32(fmaxf((d.x + bia0) * s0 + t0, 0.f));
            g_h2p[q * HALF + o1] = to_tf32(fmaxf((d.y + bia1) * s1 + t1, 0.f));
            int r2 = r + 8;
            int q2 = (r2 >> 3) * 10 + (r2 & 7) + 1;
            g_h2p[q2 * HALF + o0] = to_tf32(fmaxf((d.z + bia0) * s0 + t0, 0.f));
            g_h2p[q2 * HALF + o1] = to_tf32(fmaxf((d.w + bia1) * s1 + t1, 0.f));
        }
    }
}

// ---------------- c2 GEMM: conv k=3 as [80000,192] x [192,64] -> h3 (bn3+relu) ----
#define C2_AS 196
#define C2_BS 68
#define C2_SMEM ((64*C2_AS + 192*C2_BS) * 4)

__global__ __launch_bounds__(256) void c2_gemm(const float* __restrict__ c2b)
{
    extern __shared__ float sm[];
    float* Asm = sm;                 // [64][C2_AS]
    float* Bsm = sm + 64 * C2_AS;    // [192][C2_BS]

    int r0 = blockIdx.x * 64;
    int nb = r0 >> 3;                // line base (r0 multiple of 64 -> 8 whole lines)
    int t = threadIdx.x;
    int w = t >> 5, lane = t & 31, g = lane >> 2, tg = lane & 3;
    int m_base = (w & 3) * 16;
    int n_base = (w >> 2) * 32;

#pragma unroll
    for (int i = 0; i < 12; i++) {
        int f = t + 256 * i;             // 3072 float4: 64 rows x 48
        int row = f / 48, c4 = (f % 48) * 4;
        int q = (nb + (row >> 3)) * 10 + (row & 7);   // contiguous rows q,q+1,q+2
        cp_async16(&Asm[row * C2_AS + c4], &g_h2p[q * HALF + c4]);
    }
#pragma unroll
    for (int i = 0; i < 12; i++) {
        int f = t + 256 * i;             // 3072 float4: 192 rows x 16
        int row = f >> 4, c4 = (f & 15) * 4;
        cp_async16(&Bsm[row * C2_BS + c4], &g_c2wG[row * HALF + c4]);
    }
    asm volatile("cp.async.commit_group;\ncp.async.wait_group 0;\n");
    __syncthreads();

    float4 acc[4];
#pragma unroll
    for (int ni = 0; ni < 4; ni++) acc[ni] = make_float4(0.f,0.f,0.f,0.f);

#pragma unroll
    for (int ks = 0; ks < 24; ks++) {
        int kb = ks * 8;
        float afr[4];
        {
            int r = m_base + g;
            afr[0] = Asm[r * C2_AS + kb + tg];
            afr[1] = Asm[(r + 8) * C2_AS + kb + tg];
            afr[2] = Asm[r * C2_AS + kb + tg + 4];
            afr[3] = Asm[(r + 8) * C2_AS + kb + tg + 4];
        }
        float bfr[4][2];
#pragma unroll
        for (int ni = 0; ni < 4; ni++) {
            int c = n_base + ni * 8 + g;
            bfr[ni][0] = Bsm[(kb + tg) * C2_BS + c];
            bfr[ni][1] = Bsm[(kb + tg + 4) * C2_BS + c];
        }
#pragma unroll
        for (int ni = 0; ni < 4; ni++)
            mma_tf32(acc[ni], afr, bfr[ni]);
    }

#pragma unroll
    for (int ni = 0; ni < 4; ni++) {
        int o0 = n_base + ni * 8 + 2 * tg, o1 = o0 + 1;
        float bia0 = __ldg(&c2b[o0]), bia1 = __ldg(&c2b[o1]);
        float s0 = g_bn3s[o0], t0 = g_bn3t[o0];
        float s1 = g_bn3s[o1], t1 = g_bn3t[o1];
        float4 d = acc[ni];
        int r = r0 + m_base + g;
        g_h3[r * HALF + o0] = to_tf32(fmaxf((d.x + bia0) * s0 + t0, 0.f));
        g_h3[r * HALF + o1] = to_tf32(fmaxf((d.y + bia1) * s1 + t1, 0.f));
        g_h3[(r + 8) * HALF + o0] = to_tf32(fmaxf((d.z + bia0) * s0 + t0, 0.f));
        g_h3[(r + 8) * HALF + o1] = to_tf32(fmaxf((d.w + bia1) * s1 + t1, 0.f));
    }
}

// ---------------- c3 GEMM: [80000,64] x [64,128] + residual + relu -> y flat ----
#define C3_AS 68
#define C3_BS 132
#define C3_SMEM ((128*C3_AS + 64*C3_BS) * 4)

__global__ __launch_bounds__(256) void c3_gemm(const float* __restrict__ c3b)
{
    extern __shared__ float sm[];
    float* Asm = sm;                 // [128][C3_AS]
    float* Bsm = sm + 128 * C3_AS;   // [64][C3_BS]

    int r0 = blockIdx.x * 128;
    int t = threadIdx.x;
    int w = t >> 5, lane = t & 31, g = lane >> 2, tg = lane & 3;
    int m_base = (w & 3) * 32;
    int n_base = (w >> 2) * 64;

#pragma unroll
    for (int i = 0; i < 8; i++) {
        int f = t + 256 * i;             // 2048 float4: 128 rows x 16
        int row = f >> 4, c4 = (f & 15) * 4;
        cp_async16(&Asm[row * C3_AS + c4], &g_h3[(size_t)(r0 + row) * HALF + c4]);
    }
#pragma unroll
    for (int i = 0; i < 8; i++) {
        int f = t + 256 * i;             // 2048 float4: 64 rows x 32
        int row = f >> 5, c4 = (f & 31) * 4;
        cp_async16(&Bsm[row * C3_BS + c4], &g_c3wT[row * DLOI + c4]);
    }
    asm volatile("cp.async.commit_group;\ncp.async.wait_group 0;\n");
    __syncthreads();

    float4 acc[2][8];
#pragma unroll
    for (int mi = 0; mi < 2; mi++)
#pragma unroll
        for (int ni = 0; ni < 8; ni++) acc[mi][ni] = make_float4(0.f,0.f,0.f,0.f);

#pragma unroll
    for (int ks = 0; ks < 8; ks++) {
        int kb = ks * 8;
        float afr[2][4];
#pragma unroll
        for (int mi = 0; mi < 2; mi++) {
            int r = m_base + mi * 16 + g;
            afr[mi][0] = Asm[r * C3_AS + kb + tg];
            afr[mi][1] = Asm[(r + 8) * C3_AS + kb + tg];
            afr[mi][2] = Asm[r * C3_AS + kb + tg + 4];
            afr[mi][3] = Asm[(r + 8) * C3_AS + kb + tg + 4];
        }
        float bfr[8][2];
#pragma unroll
        for (int ni = 0; ni < 8; ni++) {
            int c = n_base + ni * 8 + g;
            bfr[ni][0] = Bsm[(kb + tg) * C3_BS + c];
            bfr[ni][1] = Bsm[(kb + tg + 4) * C3_BS + c];
        }
#pragma unroll
        for (int mi = 0; mi < 2; mi++)
#pragma unroll
            for (int ni = 0; ni < 8; ni++)
                mma_tf32(acc[mi][ni], afr[mi], bfr[ni]);
    }

#pragma unroll
    for (int ni = 0; ni < 8; ni++) {
        int o0 = n_base + ni * 8 + 2 * tg, o1 = o0 + 1;
        float bia0 = __ldg(&c3b[o0]), bia1 = __ldg(&c3b[o1]);
#pragma unroll
        for (int mi = 0; mi < 2; mi++) {
            float4 d = acc[mi][ni];
            int r = r0 + m_base + mi * 16 + g;
            int n1 = r >> 3, p1 = r & 7;
            g_y[(size_t)n1 * 1024 + o0 * 8 + p1] =
                fmaxf(d.x + bia0 + __ldg(&g_xp[(size_t)r * DLOI + o0]), 0.f);
            g_y[(size_t)n1 * 1024 + o1 * 8 + p1] =
                fmaxf(d.y + bia1 + __ldg(&g_xp[(size_t)r * DLOI + o1]), 0.f);
            int r2 = r + 8;
            int n2 = r2 >> 3, p2 = r2 & 7;
            g_y[(size_t)n2 * 1024 + o0 * 8 + p2] =
                fmaxf(d.z + bia0 + __ldg(&g_xp[(size_t)r2 * DLOI + o0]), 0.f);
            g_y[(size_t)n2 * 1024 + o1 * 8 + p2] =
                fmaxf(d.w + bia1 + __ldg(&g_xp[(size_t)r2 * DLOI + o1]), 0.f);
        }
    }
}

// ---------------- fc2 + softmax: 8 lines per block (1 warp each) ----------------
__global__ __launch_bounds__(256) void fc2_softmax(const float* __restrict__ wfc2,
                                                   const float* __restrict__ bfc2,
                                                   float* __restrict__ out)
{
    __shared__ float sw[4 * 1024];
    int t = threadIdx.x;
#pragma unroll
    for (int i = 0; i < 4; i++) {
        int f = t + 256 * i;
        *(float4*)&sw[f * 4] = __ldg((const float4*)&wfc2[f * 4]);
    }
    __syncthreads();

    int wid = t >> 5, lane = t & 31;
    int n = blockIdx.x * 8 + wid;
    const float* Y = g_y + (size_t)n * 1024;

    float s0 = 0.f, s1 = 0.f, s2 = 0.f, s3 = 0.f;
#pragma unroll
    for (int j = 0; j < 8; j++) {
        int idx = lane * 4 + j * 128;
        float4 yv = __ldg((const float4*)&Y[idx]);
        float4 w0 = *(const float4*)&sw[idx];
        float4 w1 = *(const float4*)&sw[1024 + idx];
        float4 w2 = *(const float4*)&sw[2048 + idx];
        float4 w3 = *(const float4*)&sw[3072 + idx];
        s0 += yv.x * w0.x + yv.y * w0.y + yv.z * w0.z + yv.w * w0.w;
        s1 += yv.x * w1.x + yv.y * w1.y + yv.z * w1.z + yv.w * w1.w;
        s2 += yv.x * w2.x + yv.y * w2.y + yv.z * w2.z + yv.w * w2.w;
        s3 += yv.x * w3.x + yv.y * w3.y + yv.z * w3.z + yv.w * w3.w;
    }
#pragma unroll
    for (int off = 16; off; off >>= 1) {
        s0 += __shfl_down_sync(0xffffffffu, s0, off);
        s1 += __shfl_down_sync(0xffffffffu, s1, off);
        s2 += __shfl_down_sync(0xffffffffu, s2, off);
        s3 += __shfl_down_sync(0xffffffffu, s3, off);
    }
    if (lane == 0) {
        float z0 = s0 + bfc2[0], z1 = s1 + bfc2[1], z2 = s2 + bfc2[2], z3 = s3 + bfc2[3];
        float m = fmaxf(fmaxf(z0, z1), fmaxf(z2, z3));
        float e0 = expf(z0 - m), e1 = expf(z1 - m), e2 = expf(z2 - m), e3 = expf(z3 - m);
        float inv = 1.0f / (e0 + e1 + e2 + e3);
        float4 r = make_float4(e0 * inv, e1 * inv, e2 * inv, e3 * inv);
        *(float4*)&out[(size_t)n * 4] = r;
    }
}

// ---------------- launch ----------------
extern "C" void kernel_launch(void* const* d_in, const int* in_sizes, int n_in,
                              void* d_out, int out_size)
{
    const float* feature = (const float*)d_in[0];
    const float* lines   = (const float*)d_in[1];
    const float* w_fc1   = (const float*)d_in[2];
    const float* b_fc1   = (const float*)d_in[3];
    const float* bn1     = (const float*)d_in[4];
    const float* c1_w    = (const float*)d_in[5];
    const float* c1_b    = (const float*)d_in[6];
    const float* bn2     = (const float*)d_in[7];
    const float* c2_w    = (const float*)d_in[8];
    const float* c2_b    = (const float*)d_in[9];
    const float* bn3     = (const float*)d_in[10];
    const float* c3_w    = (const float*)d_in[11];
    const float* c3_b    = (const float*)d_in[12];
    const float* w_fc2   = (const float*)d_in[13];
    const float* b_fc2   = (const float*)d_in[14];
    float* out = (float*)d_out;

    static int attr_set = 0;
    if (!attr_set) {
        cudaFuncSetAttribute(fc1_gemm_tf32, cudaFuncAttributeMaxDynamicSharedMemorySize, FC1_SMEM);
        cudaFuncSetAttribute(c1_gemm, cudaFuncAttributeMaxDynamicSharedMemorySize, C1_SMEM);
        cudaFuncSetAttribute(c2_gemm, cudaFuncAttributeMaxDynamicSharedMemorySize, C2_SMEM);
        cudaFuncSetAttribute(c3_gemm, cudaFuncAttributeMaxDynamicSharedMemorySize, C3_SMEM);
        attr_set = 1;
    }

    prep_kernel<<<64, 256>>>(w_fc1, bn1, c1_w, bn2, c2_w, bn3, c3_w);

    dim3 grid(HW / 256, BQ);
    fc1_gemm_tf32<<<grid, 256, FC1_SMEM>>>(feature, b_fc1);

    line_gather<<<NL, 128>>>(lines);
    c1_gemm<<<RROWS / 128, 256, C1_SMEM>>>(c1_b);
    c2_gemm<<<RROWS / 64, 256, C2_SMEM>>>(c2_b);
    c3_gemm<<<RROWS / 128, 256, C3_SMEM>>>(c3_b);
    fc2_softmax<<<NL / 8, 256>>>(w_fc2, b_fc2, out);
}

// round 12
// speedup vs baseline: 2.0847x; 1.0876x over previous
#include <cuda_runtime.h>
#include <cuda_fp16.h>
#include <stdint.h>
#include <math.h>

#define BQ 2
#define LQ 5000
#define NL (BQ*LQ)
#define RROWS (NL*8)
#define CIN 256
#define DLOI 128
#define NPTS0 32
#define NPTS1 8
#define HH 256
#define HALF 64
#define HW (HH*HH)
#define EPSBN 1e-5f

// ---------------- scratch (device globals; no allocation allowed) ----------------
__device__ __half g_xh[BQ * HW * DLOI];        // fc1 output, NHWC, fp16 (33.5 MB)
__device__ float g_wfc1T[CIN * DLOI];          // [k][o], tf32-rounded (fc1 B operand)
__device__ __half g_c1wH[HALF * DLOI];         // [o][k=c]  (original layout, fp16)
__device__ __half g_c2wH[HALF * 192];          // [o][k=dk*64+i]
__device__ __half g_c3wH[DLOI * HALF];         // [o][k=i]
__device__ float g_bn1s[DLOI], g_bn1t[DLOI];
__device__ float g_bn2s[HALF], g_bn2t[HALF];
__device__ float g_bn3s[HALF], g_bn3t[HALF];
// line pipeline buffers (fp16)
__device__ __half g_h1h[RROWS * DLOI];         // bn1+relu(xp)   (20.5 MB)
__device__ __half g_xph[RROWS * DLOI];         // raw pooled residual (20.5 MB)
__device__ __half g_h2ph[NL * 10 * HALF];      // padded rows; pads stay zero (12.8 MB)
__device__ __half g_h3h[RROWS * HALF];         // (10.2 MB)
__device__ float g_y[NL * DLOI * NPTS1];       // relu(xp + c3out), flat [n][c*8+p] (41 MB)

__device__ __forceinline__ float to_tf32(float x) {
    uint32_t r;
    asm("cvt.rna.tf32.f32 %0, %1;" : "=r"(r) : "f"(x));
    return __uint_as_float(r);
}

// ---------------- prep: convert weights, fold BN ----------------
__global__ void prep_kernel(const float* __restrict__ w_fc1,
                            const float* __restrict__ bn1,
                            const float* __restrict__ c1w,
                            const float* __restrict__ bn2,
                            const float* __restrict__ c2w,
                            const float* __restrict__ bn3,
                            const float* __restrict__ c3w)
{
    int t = blockIdx.x * blockDim.x + threadIdx.x;
    int stride = gridDim.x * blockDim.x;
    for (int idx = t; idx < DLOI * CIN; idx += stride) {
        int o = idx / CIN, k = idx % CIN;
        g_wfc1T[k * DLOI + o] = to_tf32(w_fc1[idx]);
    }
    for (int idx = t; idx < HALF * DLOI; idx += stride) {
        g_c1wH[idx] = __float2half_rn(c1w[idx]);          // [o][c] direct
    }
    for (int idx = t; idx < HALF * HALF * 3; idx += stride) {
        // c2w: [o][i][dk] -> g_c2wH[o][dk*64+i]
        int o = idx / (HALF * 3), rem = idx % (HALF * 3);
        int i = rem / 3, dk = rem % 3;
        g_c2wH[o * 192 + dk * HALF + i] = __float2half_rn(c2w[idx]);
    }
    for (int idx = t; idx < DLOI * HALF; idx += stride) {
        g_c3wH[idx] = __float2half_rn(c3w[idx]);          // [o][i] direct
    }
    for (int idx = t; idx < DLOI; idx += stride) {
        float g = bn1[idx], be = bn1[DLOI + idx], mu = bn1[2*DLOI + idx], va = bn1[3*DLOI + idx];
        float s = g * rsqrtf(va + EPSBN);
        g_bn1s[idx] = s; g_bn1t[idx] = be - mu * s;
    }
    for (int idx = t; idx < HALF; idx += stride) {
        float g = bn2[idx], be = bn2[HALF + idx], mu = bn2[2*HALF + idx], va = bn2[3*HALF + idx];
        float s = g * rsqrtf(va + EPSBN);
        g_bn2s[idx] = s; g_bn2t[idx] = be - mu * s;
        float g3 = bn3[idx], be3 = bn3[HALF + idx], mu3 = bn3[2*HALF + idx], va3 = bn3[3*HALF + idx];
        float s3 = g3 * rsqrtf(va3 + EPSBN);
        g_bn3s[idx] = s3; g_bn3t[idx] = be3 - mu3 * s3;
    }
}

// ---------------- MMA helpers ----------------
__device__ __forceinline__ void cp_async16(void* smem_ptr, const void* gmem_ptr) {
    uint32_t s = (uint32_t)__cvta_generic_to_shared(smem_ptr);
    asm volatile("cp.async.cg.shared.global [%0], [%1], 16;\n" :: "r"(s), "l"(gmem_ptr));
}

__device__ __forceinline__ void mma_tf32(float4& d, const float* a, const float* b) {
    asm volatile(
        "mma.sync.aligned.m16n8k8.row.col.f32.tf32.tf32.f32 "
        "{%0,%1,%2,%3}, {%4,%5,%6,%7}, {%8,%9}, {%0,%1,%2,%3};\n"
        : "+f"(d.x), "+f"(d.y), "+f"(d.z), "+f"(d.w)
        : "r"(__float_as_uint(a[0])), "r"(__float_as_uint(a[1])),
          "r"(__float_as_uint(a[2])), "r"(__float_as_uint(a[3])),
          "r"(__float_as_uint(b[0])), "r"(__float_as_uint(b[1])));
}

__device__ __forceinline__ void mma_f16(float4& d, const uint32_t* a, const uint32_t* b) {
    asm volatile(
        "mma.sync.aligned.m16n8k16.row.col.f32.f16.f16.f32 "
        "{%0,%1,%2,%3}, {%4,%5,%6,%7}, {%8,%9}, {%0,%1,%2,%3};\n"
        : "+f"(d.x), "+f"(d.y), "+f"(d.z), "+f"(d.w)
        : "r"(a[0]), "r"(a[1]), "r"(a[2]), "r"(a[3]), "r"(b[0]), "r"(b[1]));
}

__device__ __forceinline__ uint32_t lds_u32(const __half* p) {
    return *(const uint32_t*)p;
}

// ---------------- fc1 GEMM: BM=256 x BN=128, tf32 mma.sync + cp.async ----------
#define KT 32
#define ASTR 260
#define BSTR 132
#define OSH 136
#define STAGE_FLOATS (KT * ASTR + KT * BSTR)
#define FC1_SMEM (2 * STAGE_FLOATS * 4)

__global__ __launch_bounds__(256) void fc1_gemm_tf32(const float* __restrict__ feat,
                                                     const float* __restrict__ bfc1)
{
    extern __shared__ float sm[];

    int b  = blockIdx.y;
    int p0 = blockIdx.x * 256;
    const float* A = feat + (size_t)b * CIN * HW;
    __half* O = g_xh + (size_t)b * HW * DLOI;

    int t    = threadIdx.x;
    int w    = t >> 5;
    int lane = t & 31;
    int g    = lane >> 2;
    int tg   = lane & 3;
    int warp_m = w & 3;
    int warp_n = w >> 2;
    int m_base = warp_m * 64;
    int n_base = warp_n * 64;

    float4 acc[4][8];
#pragma unroll
    for (int mi = 0; mi < 4; mi++)
#pragma unroll
        for (int ni = 0; ni < 8; ni++) acc[mi][ni] = make_float4(0.f, 0.f, 0.f, 0.f);

    auto issue_stage = [&](int s) {
        float* As = sm + (s & 1) * STAGE_FLOATS;
        float* Bs = As + KT * ASTR;
        int k0 = s * KT;
#pragma unroll
        for (int i = 0; i < 8; i++) {
            int f  = t + 256 * i;
            int kk = f >> 6;
            int pm = (f & 63) * 4;
            cp_async16(&As[kk * ASTR + pm], &A[(size_t)(k0 + kk) * HW + p0 + pm]);
        }
#pragma unroll
        for (int i = 0; i < 4; i++) {
            int f  = t + 256 * i;
            int kk = f >> 5;
            int pm = (f & 31) * 4;
            cp_async16(&Bs[kk * BSTR + pm], &g_wfc1T[(k0 + kk) * DLOI + pm]);
        }
        asm volatile("cp.async.commit_group;\n");
    };

    issue_stage(0);

    const int NS = CIN / KT;
    for (int s = 0; s < NS; s++) {
        if (s + 1 < NS) {
            issue_stage(s + 1);
            asm volatile("cp.async.wait_group 1;\n");
        } else {
            asm volatile("cp.async.wait_group 0;\n");
        }
        __syncthreads();

        float* As = sm + (s & 1) * STAGE_FLOATS;
        float* Bs = As + KT * ASTR;

#pragma unroll
        for (int ks = 0; ks < KT / 8; ks++) {
            int kb = ks * 8;
            float afr[4][4];
#pragma unroll
            for (int mi = 0; mi < 4; mi++) {
                int r = m_base + mi * 16 + g;
                afr[mi][0] = As[(kb + tg) * ASTR + r];
                afr[mi][1] = As[(kb + tg) * ASTR + r + 8];
                afr[mi][2] = As[(kb + tg + 4) * ASTR + r];
                afr[mi][3] = As[(kb + tg + 4) * ASTR + r + 8];
            }
            float bfr[8][2];
#pragma unroll
            for (int ni = 0; ni < 8; ni++) {
                int c = n_base + ni * 8 + g;
                bfr[ni][0] = Bs[(kb + tg) * BSTR + c];
                bfr[ni][1] = Bs[(kb + tg + 4) * BSTR + c];
            }
#pragma unroll
            for (int mi = 0; mi < 4; mi++)
#pragma unroll
                for (int ni = 0; ni < 8; ni++)
                    mma_tf32(acc[mi][ni], afr[mi], bfr[ni]);
        }
        __syncthreads();
    }

    float bx[8], by[8];
#pragma unroll
    for (int ni = 0; ni < 8; ni++) {
        int c = n_base + ni * 8 + 2 * tg;
        bx[ni] = bfc1[c];
        by[ni] = bfc1[c + 1];
    }

    __half* Osm = (__half*)sm;
#pragma unroll
    for (int chunk = 0; chunk < 4; chunk++) {
        if (warp_m == chunk) {
#pragma unroll
            for (int mi = 0; mi < 4; mi++) {
#pragma unroll
                for (int ni = 0; ni < 8; ni++) {
                    int row = mi * 16 + g;
                    int col = n_base + ni * 8 + 2 * tg;
                    float4 d = acc[mi][ni];
                    *(__half2*)&Osm[row * OSH + col] =
                        __floats2half2_rn(d.x + bx[ni], d.y + by[ni]);
                    *(__half2*)&Osm[(row + 8) * OSH + col] =
                        __floats2half2_rn(d.z + bx[ni], d.w + by[ni]);
                }
            }
        }
        __syncthreads();
#pragma unroll
        for (int i = 0; i < 4; i++) {
            int f   = t + 256 * i;
            int row = f >> 4;
            int h0  = (f & 15) * 8;
            uint4 v = *(const uint4*)&Osm[row * OSH + h0];
            *(uint4*)&O[(size_t)(p0 + chunk * 64 + row) * DLOI + h0] = v;
        }
        __syncthreads();
    }
}

// ---------------- line_gather: geometry + bilinear + maxpool -> g_h1h, g_xph ----
__global__ __launch_bounds__(128) void line_gather(const float* __restrict__ lines)
{
    __shared__ int4   soff[NPTS0];
    __shared__ float4 swt[NPTS0];

    int n = blockIdx.x;
    int t = threadIdx.x;
    int b = n / LQ;

    if (t < NPTS0) {
        const float* ln = lines + (size_t)n * 4;
        float ax = __ldg(ln), ay = __ldg(ln + 1), bx = __ldg(ln + 2), by = __ldg(ln + 3);
        float lam = (float)t * (1.0f / 31.0f);
        float px = ax * lam + bx * (1.0f - lam) - 0.5f;
        float py = ay * lam + by * (1.0f - lam) - 0.5f;
        float px0 = fminf(fmaxf(floorf(px), 0.0f), 255.0f);
        float py0 = fminf(fmaxf(floorf(py), 0.0f), 255.0f);
        float px1 = fminf(px0 + 1.0f, 255.0f);
        float py1 = fminf(py0 + 1.0f, 255.0f);
        int i0 = (int)px0, j0 = (int)py0, i1 = (int)px1, j1 = (int)py1;
        float w00 = (px1 - px) * (py1 - py);
        float w10 = (px - px0) * (py1 - py);
        float w01 = (px1 - px) * (py - py0);
        float w11 = (px - px0) * (py - py0);
        soff[t] = make_int4(((i0 << 8) + j0) << 6, ((i1 << 8) + j0) << 6,
                            ((i0 << 8) + j1) << 6, ((i1 << 8) + j1) << 6);
        swt[t] = make_float4(w00, w10, w01, w11);
    }
    __syncthreads();

    int c2 = t & 63, ph = t >> 6;
    const __half2* X2 = (const __half2*)g_xh + (size_t)b * HW * 64 + c2;

    int ca = 2 * c2, cb = 2 * c2 + 1;
    float sa = g_bn1s[ca], ta = g_bn1t[ca];
    float sb = g_bn1s[cb], tb = g_bn1t[cb];

#pragma unroll
    for (int pp = 0; pp < 4; pp++) {
        float2 m = make_float2(-INFINITY, -INFINITY);
#pragma unroll
        for (int kk = 0; kk < 4; kk++) {
            int k = (ph * 4 + pp) * 4 + kk;
            int4  o4 = soff[k];
            float4 w4 = swt[k];
            float2 h00 = __half22float2(__ldg(X2 + o4.x));
            float2 h10 = __half22float2(__ldg(X2 + o4.y));
            float2 h01 = __half22float2(__ldg(X2 + o4.z));
            float2 h11 = __half22float2(__ldg(X2 + o4.w));
            float vx = h00.x * w4.x + h10.x * w4.y + h01.x * w4.z + h11.x * w4.w;
            float vy = h00.y * w4.x + h10.y * w4.y + h01.y * w4.z + h11.y * w4.w;
            m.x = fmaxf(m.x, vx);
            m.y = fmaxf(m.y, vy);
        }
        int p = ph * 4 + pp;
        size_t base = ((size_t)n * 8 + p) * DLOI + ca;
        *(__half2*)&g_xph[base] = __floats2half2_rn(m.x, m.y);
        *(__half2*)&g_h1h[base] = __floats2half2_rn(
            fmaxf(m.x * sa + ta, 0.f), fmaxf(m.y * sb + tb, 0.f));
    }
}

// ---------------- c1 GEMM (fp16): [80000,128] x [128,64] -> h2p (bn2+relu) ----
#define C1_AS 136      // halves
#define C1_BS 136
#define C1_SMEM ((128*C1_AS + 64*C1_BS) * 2)

__global__ __launch_bounds__(256) void c1_gemm(const float* __restrict__ c1b)
{
    extern __shared__ __half smh[];
    __half* Asm = smh;                 // [128 m][C1_AS k]
    __half* Bsm = smh + 128 * C1_AS;   // [64 n][C1_BS k]

    int r0 = blockIdx.x * 128;
    int t = threadIdx.x;
    int w = t >> 5, lane = t & 31, g = lane >> 2, tg = lane & 3;
    int m_base = (w & 3) * 32;
    int n_base = (w >> 2) * 32;

#pragma unroll
    for (int i = 0; i < 8; i++) {
        int f = t + 256 * i;             // 2048 chunks: 128 rows x 16
        int row = f >> 4, c8 = (f & 15) * 8;
        cp_async16(&Asm[row * C1_AS + c8], &g_h1h[(size_t)(r0 + row) * DLOI + c8]);
    }
#pragma unroll
    for (int i = 0; i < 4; i++) {
        int f = t + 256 * i;             // 1024 chunks: 64 rows x 16
        int row = f >> 4, c8 = (f & 15) * 8;
        cp_async16(&Bsm[row * C1_BS + c8], &g_c1wH[row * DLOI + c8]);
    }
    asm volatile("cp.async.commit_group;\ncp.async.wait_group 0;\n");
    __syncthreads();

    float4 acc[2][4];
#pragma unroll
    for (int mi = 0; mi < 2; mi++)
#pragma unroll
        for (int ni = 0; ni < 4; ni++) acc[mi][ni] = make_float4(0.f,0.f,0.f,0.f);

#pragma unroll
    for (int ks = 0; ks < 8; ks++) {
        int kb = ks * 16;
        uint32_t afr[2][4];
#pragma unroll
        for (int mi = 0; mi < 2; mi++) {
            int r = m_base + mi * 16 + g;
            afr[mi][0] = lds_u32(&Asm[r * C1_AS + kb + 2*tg]);
            afr[mi][1] = lds_u32(&Asm[(r + 8) * C1_AS + kb + 2*tg]);
            afr[mi][2] = lds_u32(&Asm[r * C1_AS + kb + 2*tg + 8]);
            afr[mi][3] = lds_u32(&Asm[(r + 8) * C1_AS + kb + 2*tg + 8]);
        }
        uint32_t bfr[4][2];
#pragma unroll
        for (int ni = 0; ni < 4; ni++) {
            int c = n_base + ni * 8 + g;
            bfr[ni][0] = lds_u32(&Bsm[c * C1_BS + kb + 2*tg]);
            bfr[ni][1] = lds_u32(&Bsm[c * C1_BS + kb + 2*tg + 8]);
        }
#pragma unroll
        for (int mi = 0; mi < 2; mi++)
#pragma unroll
            for (int ni = 0; ni < 4; ni++)
                mma_f16(acc[mi][ni], afr[mi], bfr[ni]);
    }

#pragma unroll
    for (int ni = 0; ni < 4; ni++) {
        int o0 = n_base + ni * 8 + 2 * tg, o1 = o0 + 1;
        float bia0 = __ldg(&c1b[o0]), bia1 = __ldg(&c1b[o1]);
        float s0 = g_bn2s[o0], t0 = g_bn2t[o0];
        float s1 = g_bn2s[o1], t1 = g_bn2t[o1];
#pragma unroll
        for (int mi = 0; mi < 2; mi++) {
            float4 d = acc[mi][ni];
            int r = r0 + m_base + mi * 16 + g;
            int q = (r >> 3) * 10 + (r & 7) + 1;
            g_h2ph[q * HALF + o0] = __float2half_rn(fmaxf((d.x + bia0) * s0 + t0, 0.f));
            g_h2ph[q * HALF + o1] = __float2half_rn(fmaxf((d.y + bia1) * s1 + t1, 0.f));
            int r2 = r + 8;
            int q2 = (r2 >> 3) * 10 + (r2 & 7) + 1;
            g_h2ph[q2 * HALF + o0] = __float2half_rn(fmaxf((d.z + bia0) * s0 + t0, 0.f));
            g_h2ph[q2 * HALF + o1] = __float2half_rn(fmaxf((d.w + bia1) * s1 + t1, 0.f));
        }
    }
}

// ---------------- c2 GEMM (fp16): conv k=3 as [80000,192] x [192,64] -> h3 ----
#define C2_AS 200      // halves (192 + 8)
#define C2_BS 200
#define C2_SMEM ((64*C2_AS + 64*C2_BS) * 2)

__global__ __launch_bounds__(256) void c2_gemm(const float* __restrict__ c2b)
{
    extern __shared__ __half smh[];
    __half* Asm = smh;                // [64 m][C2_AS]
    __half* Bsm = smh + 64 * C2_AS;   // [64 n][C2_BS]

    int r0 = blockIdx.x * 64;
    int nb = r0 >> 3;
    int t = threadIdx.x;
    int w = t >> 5, lane = t & 31, g = lane >> 2, tg = lane & 3;
    int m_base = (w & 3) * 16;
    int n_base = (w >> 2) * 32;

#pragma unroll
    for (int i = 0; i < 6; i++) {
        int f = t + 256 * i;             // 1536 chunks: 64 rows x 24
        int row = f / 24, c8 = (f % 24) * 8;
        int q = (nb + (row >> 3)) * 10 + (row & 7);
        cp_async16(&Asm[row * C2_AS + c8], &g_h2ph[q * HALF + c8]);
    }
#pragma unroll
    for (int i = 0; i < 6; i++) {
        int f = t + 256 * i;             // 1536 chunks: 64 rows x 24
        int row = f / 24, c8 = (f % 24) * 8;
        cp_async16(&Bsm[row * C2_BS + c8], &g_c2wH[row * 192 + c8]);
    }
    asm volatile("cp.async.commit_group;\ncp.async.wait_group 0;\n");
    __syncthreads();

    float4 acc[4];
#pragma unroll
    for (int ni = 0; ni < 4; ni++) acc[ni] = make_float4(0.f,0.f,0.f,0.f);

#pragma unroll
    for (int ks = 0; ks < 12; ks++) {
        int kb = ks * 16;
        uint32_t afr[4];
        {
            int r = m_base + g;
            afr[0] = lds_u32(&Asm[r * C2_AS + kb + 2*tg]);
            afr[1] = lds_u32(&Asm[(r + 8) * C2_AS + kb + 2*tg]);
            afr[2] = lds_u32(&Asm[r * C2_AS + kb + 2*tg + 8]);
            afr[3] = lds_u32(&Asm[(r + 8) * C2_AS + kb + 2*tg + 8]);
        }
        uint32_t bfr[4][2];
#pragma unroll
        for (int ni = 0; ni < 4; ni++) {
            int c = n_base + ni * 8 + g;
            bfr[ni][0] = lds_u32(&Bsm[c * C2_BS + kb + 2*tg]);
            bfr[ni][1] = lds_u32(&Bsm[c * C2_BS + kb + 2*tg + 8]);
        }
#pragma unroll
        for (int ni = 0; ni < 4; ni++)
            mma_f16(acc[ni], afr, bfr[ni]);
    }

#pragma unroll
    for (int ni = 0; ni < 4; ni++) {
        int o0 = n_base + ni * 8 + 2 * tg, o1 = o0 + 1;
        float bia0 = __ldg(&c2b[o0]), bia1 = __ldg(&c2b[o1]);
        float s0 = g_bn3s[o0], t0 = g_bn3t[o0];
        float s1 = g_bn3s[o1], t1 = g_bn3t[o1];
        float4 d = acc[ni];
        int r = r0 + m_base + g;
        g_h3h[r * HALF + o0] = __float2half_rn(fmaxf((d.x + bia0) * s0 + t0, 0.f));
        g_h3h[r * HALF + o1] = __float2half_rn(fmaxf((d.y + bia1) * s1 + t1, 0.f));
        g_h3h[(r + 8) * HALF + o0] = __float2half_rn(fmaxf((d.z + bia0) * s0 + t0, 0.f));
        g_h3h[(r + 8) * HALF + o1] = __float2half_rn(fmaxf((d.w + bia1) * s1 + t1, 0.f));
    }
}

// ---------------- c3 GEMM (fp16): [80000,64] x [64,128] + residual -> y flat ----
#define C3_AS 72       // halves (64 + 8)
#define C3_BS 72
#define C3_SMEM ((128*C3_AS + 128*C3_BS) * 2)

__global__ __launch_bounds__(256) void c3_gemm(const float* __restrict__ c3b)
{
    extern __shared__ __half smh[];
    __half* Asm = smh;                 // [128 m][C3_AS]
    __half* Bsm = smh + 128 * C3_AS;   // [128 n][C3_BS]

    int r0 = blockIdx.x * 128;
    int t = threadIdx.x;
    int w = t >> 5, lane = t & 31, g = lane >> 2, tg = lane & 3;
    int m_base = (w & 3) * 32;
    int n_base = (w >> 2) * 64;

#pragma unroll
    for (int i = 0; i < 4; i++) {
        int f = t + 256 * i;             // 1024 chunks: 128 rows x 8
        int row = f >> 3, c8 = (f & 7) * 8;
        cp_async16(&Asm[row * C3_AS + c8], &g_h3h[(size_t)(r0 + row) * HALF + c8]);
    }
#pragma unroll
    for (int i = 0; i < 4; i++) {
        int f = t + 256 * i;             // 1024 chunks: 128 rows x 8
        int row = f >> 3, c8 = (f & 7) * 8;
        cp_async16(&Bsm[row * C3_BS + c8], &g_c3wH[row * HALF + c8]);
    }
    asm volatile("cp.async.commit_group;\ncp.async.wait_group 0;\n");
    __syncthreads();

    float4 acc[2][8];
#pragma unroll
    for (int mi = 0; mi < 2; mi++)
#pragma unroll
        for (int ni = 0; ni < 8; ni++) acc[mi][ni] = make_float4(0.f,0.f,0.f,0.f);

#pragma unroll
    for (int ks = 0; ks < 4; ks++) {
        int kb = ks * 16;
        uint32_t afr[2][4];
#pragma unroll
        for (int mi = 0; mi < 2; mi++) {
            int r = m_base + mi * 16 + g;
            afr[mi][0] = lds_u32(&Asm[r * C3_AS + kb + 2*tg]);
            afr[mi][1] = lds_u32(&Asm[(r + 8) * C3_AS + kb + 2*tg]);
            afr[mi][2] = lds_u32(&Asm[r * C3_AS + kb + 2*tg + 8]);
            afr[mi][3] = lds_u32(&Asm[(r + 8) * C3_AS + kb + 2*tg + 8]);
        }
        uint32_t bfr[8][2];
#pragma unroll
        for (int ni = 0; ni < 8; ni++) {
            int c = n_base + ni * 8 + g;
            bfr[ni][0] = lds_u32(&Bsm[c * C3_BS + kb + 2*tg]);
            bfr[ni][1] = lds_u32(&Bsm[c * C3_BS + kb + 2*tg + 8]);
        }
#pragma unroll
        for (int mi = 0; mi < 2; mi++)
#pragma unroll
            for (int ni = 0; ni < 8; ni++)
                mma_f16(acc[mi][ni], afr[mi], bfr[ni]);
    }

#pragma unroll
    for (int ni = 0; ni < 8; ni++) {
        int o0 = n_base + ni * 8 + 2 * tg, o1 = o0 + 1;
        float bia0 = __ldg(&c3b[o0]), bia1 = __ldg(&c3b[o1]);
#pragma unroll
        for (int mi = 0; mi < 2; mi++) {
            float4 d = acc[mi][ni];
            int r = r0 + m_base + mi * 16 + g;
            int n1 = r >> 3, p1 = r & 7;
            g_y[(size_t)n1 * 1024 + o0 * 8 + p1] =
                fmaxf(d.x + bia0 + __half2float(__ldg(&g_xph[(size_t)r * DLOI + o0])), 0.f);
            g_y[(size_t)n1 * 1024 + o1 * 8 + p1] =
                fmaxf(d.y + bia1 + __half2float(__ldg(&g_xph[(size_t)r * DLOI + o1])), 0.f);
            int r2 = r + 8;
            int n2 = r2 >> 3, p2 = r2 & 7;
            g_y[(size_t)n2 * 1024 + o0 * 8 + p2] =
                fmaxf(d.z + bia0 + __half2float(__ldg(&g_xph[(size_t)r2 * DLOI + o0])), 0.f);
            g_y[(size_t)n2 * 1024 + o1 * 8 + p2] =
                fmaxf(d.w + bia1 + __half2float(__ldg(&g_xph[(size_t)r2 * DLOI + o1])), 0.f);
        }
    }
}

// ---------------- fc2 + softmax: 8 lines per block (1 warp each) ----------------
__global__ __launch_bounds__(256) void fc2_softmax(const float* __restrict__ wfc2,
                                                   const float* __restrict__ bfc2,
                                                   float* __restrict__ out)
{
    __shared__ float sw[4 * 1024];
    int t = threadIdx.x;
#pragma unroll
    for (int i = 0; i < 4; i++) {
        int f = t + 256 * i;
        *(float4*)&sw[f * 4] = __ldg((const float4*)&wfc2[f * 4]);
    }
    __syncthreads();

    int wid = t >> 5, lane = t & 31;
    int n = blockIdx.x * 8 + wid;
    const float* Y = g_y + (size_t)n * 1024;

    float s0 = 0.f, s1 = 0.f, s2 = 0.f, s3 = 0.f;
#pragma unroll
    for (int j = 0; j < 8; j++) {
        int idx = lane * 4 + j * 128;
        float4 yv = __ldg((const float4*)&Y[idx]);
        float4 w0 = *(const float4*)&sw[idx];
        float4 w1 = *(const float4*)&sw[1024 + idx];
        float4 w2 = *(const float4*)&sw[2048 + idx];
        float4 w3 = *(const float4*)&sw[3072 + idx];
        s0 += yv.x * w0.x + yv.y * w0.y + yv.z * w0.z + yv.w * w0.w;
        s1 += yv.x * w1.x + yv.y * w1.y + yv.z * w1.z + yv.w * w1.w;
        s2 += yv.x * w2.x + yv.y * w2.y + yv.z * w2.z + yv.w * w2.w;
        s3 += yv.x * w3.x + yv.y * w3.y + yv.z * w3.z + yv.w * w3.w;
    }
#pragma unroll
    for (int off = 16; off; off >>= 1) {
        s0 += __shfl_down_sync(0xffffffffu, s0, off);
        s1 += __shfl_down_sync(0xffffffffu, s1, off);
        s2 += __shfl_down_sync(0xffffffffu, s2, off);
        s3 += __shfl_down_sync(0xffffffffu, s3, off);
    }
    if (lane == 0) {
        float z0 = s0 + bfc2[0], z1 = s1 + bfc2[1], z2 = s2 + bfc2[2], z3 = s3 + bfc2[3];
        float m = fmaxf(fmaxf(z0, z1), fmaxf(z2, z3));
        float e0 = expf(z0 - m), e1 = expf(z1 - m), e2 = expf(z2 - m), e3 = expf(z3 - m);
        float inv = 1.0f / (e0 + e1 + e2 + e3);
        float4 r = make_float4(e0 * inv, e1 * inv, e2 * inv, e3 * inv);
        *(float4*)&out[(size_t)n * 4] = r;
    }
}

// ---------------- launch ----------------
extern "C" void kernel_launch(void* const* d_in, const int* in_sizes, int n_in,
                              void* d_out, int out_size)
{
    const float* feature = (const float*)d_in[0];
    const float* lines   = (const float*)d_in[1];
    const float* w_fc1   = (const float*)d_in[2];
    const float* b_fc1   = (const float*)d_in[3];
    const float* bn1     = (const float*)d_in[4];
    const float* c1_w    = (const float*)d_in[5];
    const float* c1_b    = (const float*)d_in[6];
    const float* bn2     = (const float*)d_in[7];
    const float* c2_w    = (const float*)d_in[8];
    const float* c2_b    = (const float*)d_in[9];
    const float* bn3     = (const float*)d_in[10];
    const float* c3_w    = (const float*)d_in[11];
    const float* c3_b    = (const float*)d_in[12];
    const float* w_fc2   = (const float*)d_in[13];
    const float* b_fc2   = (const float*)d_in[14];
    float* out = (float*)d_out;

    static int attr_set = 0;
    if (!attr_set) {
        cudaFuncSetAttribute(fc1_gemm_tf32, cudaFuncAttributeMaxDynamicSharedMemorySize, FC1_SMEM);
        cudaFuncSetAttribute(c1_gemm, cudaFuncAttributeMaxDynamicSharedMemorySize, C1_SMEM);
        cudaFuncSetAttribute(c2_gemm, cudaFuncAttributeMaxDynamicSharedMemorySize, C2_SMEM);
        cudaFuncSetAttribute(c3_gemm, cudaFuncAttributeMaxDynamicSharedMemorySize, C3_SMEM);
        attr_set = 1;
    }

    prep_kernel<<<64, 256>>>(w_fc1, bn1, c1_w, bn2, c2_w, bn3, c3_w);

    dim3 grid(HW / 256, BQ);
    fc1_gemm_tf32<<<grid, 256, FC1_SMEM>>>(feature, b_fc1);

    line_gather<<<NL, 128>>>(lines);
    c1_gemm<<<RROWS / 128, 256, C1_SMEM>>>(c1_b);
    c2_gemm<<<RROWS / 64, 256, C2_SMEM>>>(c2_b);
    c3_gemm<<<RROWS / 128, 256, C3_SMEM>>>(c3_b);
    fc2_softmax<<<NL / 8, 256>>>(w_fc2, b_fc2, out);
}

// round 14
// speedup vs baseline: 2.4915x; 1.1951x over previous
#include <cuda_runtime.h>
#include <cuda_fp16.h>
#include <stdint.h>
#include <math.h>

#define BQ 2
#define LQ 5000
#define NL (BQ*LQ)
#define RROWS (NL*8)
#define CIN 256
#define DLOI 128
#define NPTS0 32
#define NPTS1 8
#define HH 256
#define HALF 64
#define HW (HH*HH)
#define EPSBN 1e-5f

// ---------------- scratch (device globals; no allocation allowed) ----------------
__device__ __half g_xh[BQ * HW * DLOI];        // fc1 output, NHWC, fp16 (33.5 MB)
__device__ float g_wfc1T[CIN * DLOI];          // [k][o], tf32-rounded (fc1 B operand)
__device__ __half g_c1wH[HALF * DLOI];         // [o][k=c]
__device__ __half g_c2wH[HALF * 192];          // [o][k=dk*64+i]
__device__ __half g_c3wH[DLOI * HALF];         // [o][k=i]
__device__ __half g_wfc2H[4 * DLOI * NPTS1];   // [q][c*8+p] fp16
__device__ float g_bn1s[DLOI], g_bn1t[DLOI];
__device__ float g_bn2s[HALF], g_bn2t[HALF];
__device__ float g_bn3s[HALF], g_bn3t[HALF];
// line pipeline buffers (fp16)
__device__ __half g_h1h[RROWS * DLOI];         // bn1+relu(xp)
__device__ __half g_xph[RROWS * DLOI];         // raw pooled residual

__device__ __forceinline__ float to_tf32(float x) {
    uint32_t r;
    asm("cvt.rna.tf32.f32 %0, %1;" : "=r"(r) : "f"(x));
    return __uint_as_float(r);
}

// ---------------- prep: convert weights, fold BN ----------------
__global__ void prep_kernel(const float* __restrict__ w_fc1,
                            const float* __restrict__ bn1,
                            const float* __restrict__ c1w,
                            const float* __restrict__ bn2,
                            const float* __restrict__ c2w,
                            const float* __restrict__ bn3,
                            const float* __restrict__ c3w,
                            const float* __restrict__ wfc2)
{
    int t = blockIdx.x * blockDim.x + threadIdx.x;
    int stride = gridDim.x * blockDim.x;
    for (int idx = t; idx < DLOI * CIN; idx += stride) {
        int o = idx / CIN, k = idx % CIN;
        g_wfc1T[k * DLOI + o] = to_tf32(w_fc1[idx]);
    }
    for (int idx = t; idx < HALF * DLOI; idx += stride) {
        g_c1wH[idx] = __float2half_rn(c1w[idx]);
    }
    for (int idx = t; idx < HALF * HALF * 3; idx += stride) {
        int o = idx / (HALF * 3), rem = idx % (HALF * 3);
        int i = rem / 3, dk = rem % 3;
        g_c2wH[o * 192 + dk * HALF + i] = __float2half_rn(c2w[idx]);
    }
    for (int idx = t; idx < DLOI * HALF; idx += stride) {
        g_c3wH[idx] = __float2half_rn(c3w[idx]);
    }
    for (int idx = t; idx < 4 * DLOI * NPTS1; idx += stride) {
        g_wfc2H[idx] = __float2half_rn(wfc2[idx]);
    }
    for (int idx = t; idx < DLOI; idx += stride) {
        float g = bn1[idx], be = bn1[DLOI + idx], mu = bn1[2*DLOI + idx], va = bn1[3*DLOI + idx];
        float s = g * rsqrtf(va + EPSBN);
        g_bn1s[idx] = s; g_bn1t[idx] = be - mu * s;
    }
    for (int idx = t; idx < HALF; idx += stride) {
        float g = bn2[idx], be = bn2[HALF + idx], mu = bn2[2*HALF + idx], va = bn2[3*HALF + idx];
        float s = g * rsqrtf(va + EPSBN);
        g_bn2s[idx] = s; g_bn2t[idx] = be - mu * s;
        float g3 = bn3[idx], be3 = bn3[HALF + idx], mu3 = bn3[2*HALF + idx], va3 = bn3[3*HALF + idx];
        float s3 = g3 * rsqrtf(va3 + EPSBN);
        g_bn3s[idx] = s3; g_bn3t[idx] = be3 - mu3 * s3;
    }
}

// ---------------- MMA helpers ----------------
__device__ __forceinline__ void cp_async16(void* smem_ptr, const void* gmem_ptr) {
    uint32_t s = (uint32_t)__cvta_generic_to_shared(smem_ptr);
    asm volatile("cp.async.cg.shared.global [%0], [%1], 16;\n" :: "r"(s), "l"(gmem_ptr));
}

__device__ __forceinline__ void mma_tf32(float4& d, const float* a, const float* b) {
    asm volatile(
        "mma.sync.aligned.m16n8k8.row.col.f32.tf32.tf32.f32 "
        "{%0,%1,%2,%3}, {%4,%5,%6,%7}, {%8,%9}, {%0,%1,%2,%3};\n"
        : "+f"(d.x), "+f"(d.y), "+f"(d.z), "+f"(d.w)
        : "r"(__float_as_uint(a[0])), "r"(__float_as_uint(a[1])),
          "r"(__float_as_uint(a[2])), "r"(__float_as_uint(a[3])),
          "r"(__float_as_uint(b[0])), "r"(__float_as_uint(b[1])));
}

__device__ __forceinline__ void mma_f16(float4& d, const uint32_t* a, const uint32_t* b) {
    asm volatile(
        "mma.sync.aligned.m16n8k16.row.col.f32.f16.f16.f32 "
        "{%0,%1,%2,%3}, {%4,%5,%6,%7}, {%8,%9}, {%0,%1,%2,%3};\n"
        : "+f"(d.x), "+f"(d.y), "+f"(d.z), "+f"(d.w)
        : "r"(a[0]), "r"(a[1]), "r"(a[2]), "r"(a[3]), "r"(b[0]), "r"(b[1]));
}

__device__ __forceinline__ uint32_t lds_u32(const __half* p) {
    return *(const uint32_t*)p;
}

// ---------------- fc1 GEMM: BM=256 x BN=128, tf32 mma.sync + cp.async ----------
#define KT 32
#define ASTR 260
#define BSTR 132
#define OSH 136
#define STAGE_FLOATS (KT * ASTR + KT * BSTR)
#define FC1_SMEM (2 * STAGE_FLOATS * 4)

__global__ __launch_bounds__(256) void fc1_gemm_tf32(const float* __restrict__ feat,
                                                     const float* __restrict__ bfc1)
{
    extern __shared__ float sm[];

    int b  = blockIdx.y;
    int p0 = blockIdx.x * 256;
    const float* A = feat + (size_t)b * CIN * HW;
    __half* O = g_xh + (size_t)b * HW * DLOI;

    int t    = threadIdx.x;
    int w    = t >> 5;
    int lane = t & 31;
    int g    = lane >> 2;
    int tg   = lane & 3;
    int warp_m = w & 3;
    int warp_n = w >> 2;
    int m_base = warp_m * 64;
    int n_base = warp_n * 64;

    float4 acc[4][8];
#pragma unroll
    for (int mi = 0; mi < 4; mi++)
#pragma unroll
        for (int ni = 0; ni < 8; ni++) acc[mi][ni] = make_float4(0.f, 0.f, 0.f, 0.f);

    auto issue_stage = [&](int s) {
        float* As = sm + (s & 1) * STAGE_FLOATS;
        float* Bs = As + KT * ASTR;
        int k0 = s * KT;
#pragma unroll
        for (int i = 0; i < 8; i++) {
            int f  = t + 256 * i;
            int kk = f >> 6;
            int pm = (f & 63) * 4;
            cp_async16(&As[kk * ASTR + pm], &A[(size_t)(k0 + kk) * HW + p0 + pm]);
        }
#pragma unroll
        for (int i = 0; i < 4; i++) {
            int f  = t + 256 * i;
            int kk = f >> 5;
            int pm = (f & 31) * 4;
            cp_async16(&Bs[kk * BSTR + pm], &g_wfc1T[(k0 + kk) * DLOI + pm]);
        }
        asm volatile("cp.async.commit_group;\n");
    };

    issue_stage(0);

    const int NS = CIN / KT;
    for (int s = 0; s < NS; s++) {
        if (s + 1 < NS) {
            issue_stage(s + 1);
            asm volatile("cp.async.wait_group 1;\n");
        } else {
            asm volatile("cp.async.wait_group 0;\n");
        }
        __syncthreads();

        float* As = sm + (s & 1) * STAGE_FLOATS;
        float* Bs = As + KT * ASTR;

#pragma unroll
        for (int ks = 0; ks < KT / 8; ks++) {
            int kb = ks * 8;
            float afr[4][4];
#pragma unroll
            for (int mi = 0; mi < 4; mi++) {
                int r = m_base + mi * 16 + g;
                afr[mi][0] = As[(kb + tg) * ASTR + r];
                afr[mi][1] = As[(kb + tg) * ASTR + r + 8];
                afr[mi][2] = As[(kb + tg + 4) * ASTR + r];
                afr[mi][3] = As[(kb + tg + 4) * ASTR + r + 8];
            }
            float bfr[8][2];
#pragma unroll
            for (int ni = 0; ni < 8; ni++) {
                int c = n_base + ni * 8 + g;
                bfr[ni][0] = Bs[(kb + tg) * BSTR + c];
                bfr[ni][1] = Bs[(kb + tg + 4) * BSTR + c];
            }
#pragma unroll
            for (int mi = 0; mi < 4; mi++)
#pragma unroll
                for (int ni = 0; ni < 8; ni++)
                    mma_tf32(acc[mi][ni], afr[mi], bfr[ni]);
        }
        __syncthreads();
    }

    float bx[8], by[8];
#pragma unroll
    for (int ni = 0; ni < 8; ni++) {
        int c = n_base + ni * 8 + 2 * tg;
        bx[ni] = bfc1[c];
        by[ni] = bfc1[c + 1];
    }

    __half* Osm = (__half*)sm;
#pragma unroll
    for (int chunk = 0; chunk < 4; chunk++) {
        if (warp_m == chunk) {
#pragma unroll
            for (int mi = 0; mi < 4; mi++) {
#pragma unroll
                for (int ni = 0; ni < 8; ni++) {
                    int row = mi * 16 + g;
                    int col = n_base + ni * 8 + 2 * tg;
                    float4 d = acc[mi][ni];
                    *(__half2*)&Osm[row * OSH + col] =
                        __floats2half2_rn(d.x + bx[ni], d.y + by[ni]);
                    *(__half2*)&Osm[(row + 8) * OSH + col] =
                        __floats2half2_rn(d.z + bx[ni], d.w + by[ni]);
                }
            }
        }
        __syncthreads();
#pragma unroll
        for (int i = 0; i < 4; i++) {
            int f   = t + 256 * i;
            int row = f >> 4;
            int h0  = (f & 15) * 8;
            uint4 v = *(const uint4*)&Osm[row * OSH + h0];
            *(uint4*)&O[(size_t)(p0 + chunk * 64 + row) * DLOI + h0] = v;
        }
        __syncthreads();
    }
}

// ---------------- line_gather: geometry + bilinear + maxpool -> g_h1h, g_xph ----
__global__ __launch_bounds__(128) void line_gather(const float* __restrict__ lines)
{
    __shared__ int4   soff[NPTS0];
    __shared__ float4 swt[NPTS0];

    int n = blockIdx.x;
    int t = threadIdx.x;
    int b = n / LQ;

    if (t < NPTS0) {
        const float* ln = lines + (size_t)n * 4;
        float ax = __ldg(ln), ay = __ldg(ln + 1), bx = __ldg(ln + 2), by = __ldg(ln + 3);
        float lam = (float)t * (1.0f / 31.0f);
        float px = ax * lam + bx * (1.0f - lam) - 0.5f;
        float py = ay * lam + by * (1.0f - lam) - 0.5f;
        float px0 = fminf(fmaxf(floorf(px), 0.0f), 255.0f);
        float py0 = fminf(fmaxf(floorf(py), 0.0f), 255.0f);
        float px1 = fminf(px0 + 1.0f, 255.0f);
        float py1 = fminf(py0 + 1.0f, 255.0f);
        int i0 = (int)px0, j0 = (int)py0, i1 = (int)px1, j1 = (int)py1;
        float w00 = (px1 - px) * (py1 - py);
        float w10 = (px - px0) * (py1 - py);
        float w01 = (px1 - px) * (py - py0);
        float w11 = (px - px0) * (py - py0);
        soff[t] = make_int4(((i0 << 8) + j0) << 6, ((i1 << 8) + j0) << 6,
                            ((i0 << 8) + j1) << 6, ((i1 << 8) + j1) << 6);
        swt[t] = make_float4(w00, w10, w01, w11);
    }
    __syncthreads();

    int c2 = t & 63, ph = t >> 6;
    const __half2* X2 = (const __half2*)g_xh + (size_t)b * HW * 64 + c2;

    int ca = 2 * c2, cb = 2 * c2 + 1;
    float sa = g_bn1s[ca], ta = g_bn1t[ca];
    float sb = g_bn1s[cb], tb = g_bn1t[cb];

#pragma unroll
    for (int pp = 0; pp < 4; pp++) {
        float2 m = make_float2(-INFINITY, -INFINITY);
#pragma unroll
        for (int kk = 0; kk < 4; kk++) {
            int k = (ph * 4 + pp) * 4 + kk;
            int4  o4 = soff[k];
            float4 w4 = swt[k];
            float2 h00 = __half22float2(__ldg(X2 + o4.x));
            float2 h10 = __half22float2(__ldg(X2 + o4.y));
            float2 h01 = __half22float2(__ldg(X2 + o4.z));
            float2 h11 = __half22float2(__ldg(X2 + o4.w));
            float vx = h00.x * w4.x + h10.x * w4.y + h01.x * w4.z + h11.x * w4.w;
            float vy = h00.y * w4.x + h10.y * w4.y + h01.y * w4.z + h11.y * w4.w;
            m.x = fmaxf(m.x, vx);
            m.y = fmaxf(m.y, vy);
        }
        int p = ph * 4 + pp;
        size_t base = ((size_t)n * 8 + p) * DLOI + ca;
        *(__half2*)&g_xph[base] = __floats2half2_rn(m.x, m.y);
        *(__half2*)&g_h1h[base] = __floats2half2_rn(
            fmaxf(m.x * sa + ta, 0.f), fmaxf(m.y * sb + tb, 0.f));
    }
}

// ---------------- fused bottleneck + fc2 + softmax: 64 rows (8 lines) per CTA ----
// smem layout (halves):
//  Asm  [64][136]  8704   (phase1 A; later h3s [64][72])
//  h2s  [80][72]   5760
//  c1ws [64][136]  8704   (later ys [8][1024] fp16 = 8192)
//  c2ws [64][200] 12800
//  c3ws [128][72]  9216
//  wfh  [4096]     4096
#define FB_A    0
#define FB_H2   8704
#define FB_C1W  (FB_H2 + 5760)
#define FB_C2W  (FB_C1W + 8704)
#define FB_C3W  (FB_C2W + 12800)
#define FB_WF   (FB_C3W + 9216)
#define FB_TOT  (FB_WF + 4096)
#define FB_SMEM (FB_TOT * 2)

__global__ __launch_bounds__(256) void bottleneck_fused(const float* __restrict__ c1b,
                                                        const float* __restrict__ c2b,
                                                        const float* __restrict__ c3b,
                                                        const float* __restrict__ bfc2,
                                                        float* __restrict__ out)
{
    extern __shared__ __half smh[];
    __half* Asm  = smh + FB_A;     // stride 136 (phase1), then h3s stride 72
    __half* h2s  = smh + FB_H2;    // stride 72, 80 rows (10 per line, pads 0&9)
    __half* c1ws = smh + FB_C1W;   // stride 136
    __half* c2ws = smh + FB_C2W;   // stride 200
    __half* c3ws = smh + FB_C3W;   // stride 72
    __half* wfh  = smh + FB_WF;    // linear 4096
    __half* h3s  = smh + FB_A;     // alias, stride 72
    __half* ys   = smh + FB_C1W;   // alias, [8][1024]

    int r0 = blockIdx.x * 64;
    int t = threadIdx.x;
    int w = t >> 5, lane = t & 31, g = lane >> 2, tg = lane & 3;
    int m_base = (w & 3) * 16;
    int lb = m_base >> 3;          // rows m_base+g -> line lb (p=g); rows +8 -> line lb+1

    // ---- stage all inputs ----
#pragma unroll
    for (int i = 0; i < 4; i++) {          // A: 64 x 16 chunks
        int f = t + 256 * i;
        int row = f >> 4, c8 = (f & 15) * 8;
        cp_async16(&Asm[row * 136 + c8], &g_h1h[(size_t)(r0 + row) * DLOI + c8]);
    }
#pragma unroll
    for (int i = 0; i < 4; i++) {          // c1w: 64 x 16
        int f = t + 256 * i;
        int row = f >> 4, c8 = (f & 15) * 8;
        cp_async16(&c1ws[row * 136 + c8], &g_c1wH[row * DLOI + c8]);
    }
#pragma unroll
    for (int i = 0; i < 6; i++) {          // c2w: 64 x 24
        int f = t + 256 * i;
        int row = f / 24, c8 = (f % 24) * 8;
        cp_async16(&c2ws[row * 200 + c8], &g_c2wH[row * 192 + c8]);
    }
#pragma unroll
    for (int i = 0; i < 4; i++) {          // c3w: 128 x 8
        int f = t + 256 * i;
        int row = f >> 3, c8 = (f & 7) * 8;
        cp_async16(&c3ws[row * 72 + c8], &g_c3wH[row * HALF + c8]);
    }
#pragma unroll
    for (int i = 0; i < 2; i++) {          // wfc2: 512 chunks
        int f = t + 256 * i;
        cp_async16(&wfh[f * 8], &g_wfc2H[f * 8]);
    }
    asm volatile("cp.async.commit_group;\n");

    // zero h2s pad rows (16 rows x 72 halves = 576 u32)
    for (int i = t; i < 576; i += 256) {
        int pr = i / 36, word = i % 36;
        int q = (pr >> 1) * 10 + (pr & 1) * 9;
        ((uint32_t*)&h2s[q * 72])[word] = 0;
    }
    asm volatile("cp.async.wait_group 0;\n");
    __syncthreads();

    // ---- phase 1: c1  M64 K128 N64 -> h2s ----
    {
        int n_base = (w >> 2) * 32;
        float4 acc[4];
#pragma unroll
        for (int ni = 0; ni < 4; ni++) acc[ni] = make_float4(0.f,0.f,0.f,0.f);
#pragma unroll
        for (int ks = 0; ks < 8; ks++) {
            int kb = ks * 16;
            uint32_t afr[4];
            int r = m_base + g;
            afr[0] = lds_u32(&Asm[r * 136 + kb + 2*tg]);
            afr[1] = lds_u32(&Asm[(r + 8) * 136 + kb + 2*tg]);
            afr[2] = lds_u32(&Asm[r * 136 + kb + 2*tg + 8]);
            afr[3] = lds_u32(&Asm[(r + 8) * 136 + kb + 2*tg + 8]);
            uint32_t bfr[4][2];
#pragma unroll
            for (int ni = 0; ni < 4; ni++) {
                int c = n_base + ni * 8 + g;
                bfr[ni][0] = lds_u32(&c1ws[c * 136 + kb + 2*tg]);
                bfr[ni][1] = lds_u32(&c1ws[c * 136 + kb + 2*tg + 8]);
            }
#pragma unroll
            for (int ni = 0; ni < 4; ni++)
                mma_f16(acc[ni], afr, bfr[ni]);
        }
        int q1 = lb * 10 + g + 1;           // row r -> line lb, p=g, stored at p+1
        int q2 = (lb + 1) * 10 + g + 1;     // row r+8
#pragma unroll
        for (int ni = 0; ni < 4; ni++) {
            int o0 = n_base + ni * 8 + 2 * tg, o1 = o0 + 1;
            float bia0 = __ldg(&c1b[o0]), bia1 = __ldg(&c1b[o1]);
            float s0 = g_bn2s[o0], t0 = g_bn2t[o0];
            float s1 = g_bn2s[o1], t1 = g_bn2t[o1];
            float4 d = acc[ni];
            h2s[q1 * 72 + o0] = __float2half_rn(fmaxf((d.x + bia0) * s0 + t0, 0.f));
            h2s[q1 * 72 + o1] = __float2half_rn(fmaxf((d.y + bia1) * s1 + t1, 0.f));
            h2s[q2 * 72 + o0] = __float2half_rn(fmaxf((d.z + bia0) * s0 + t0, 0.f));
            h2s[q2 * 72 + o1] = __float2half_rn(fmaxf((d.w + bia1) * s1 + t1, 0.f));
        }
    }
    __syncthreads();

    // ---- phase 2: c2  M64 K192 N64 -> h3s (aliases Asm) ----
    {
        int n_base = (w >> 2) * 32;
        float4 acc[4];
#pragma unroll
        for (int ni = 0; ni < 4; ni++) acc[ni] = make_float4(0.f,0.f,0.f,0.f);
#pragma unroll
        for (int ks = 0; ks < 12; ks++) {
            int kb = ks * 16;
            int dk = kb >> 6, koff = kb & 63;
            // A[row r][dk*64+koff'] = h2[line][p-1+dk][koff'] = h2s[line*10 + p + dk]
            int qa = lb * 10 + g + dk;              // FIXED (was (lb+dk)*10+g)
            int qb = (lb + 1) * 10 + g + dk;        // FIXED
            uint32_t afr[4];
            afr[0] = lds_u32(&h2s[qa * 72 + koff + 2*tg]);
            afr[1] = lds_u32(&h2s[qb * 72 + koff + 2*tg]);
            afr[2] = lds_u32(&h2s[qa * 72 + koff + 2*tg + 8]);
            afr[3] = lds_u32(&h2s[qb * 72 + koff + 2*tg + 8]);
            uint32_t bfr[4][2];
#pragma unroll
            for (int ni = 0; ni < 4; ni++) {
                int c = n_base + ni * 8 + g;
                bfr[ni][0] = lds_u32(&c2ws[c * 200 + kb + 2*tg]);
                bfr[ni][1] = lds_u32(&c2ws[c * 200 + kb + 2*tg + 8]);
            }
#pragma unroll
            for (int ni = 0; ni < 4; ni++)
                mma_f16(acc[ni], afr, bfr[ni]);
        }
        __syncthreads();   // all Asm/h2s reads complete before h3s overwrites Asm
        int r = m_base + g;
#pragma unroll
        for (int ni = 0; ni < 4; ni++) {
            int o0 = n_base + ni * 8 + 2 * tg, o1 = o0 + 1;
            float bia0 = __ldg(&c2b[o0]), bia1 = __ldg(&c2b[o1]);
            float s0 = g_bn3s[o0], t0 = g_bn3t[o0];
            float s1 = g_bn3s[o1], t1 = g_bn3t[o1];
            float4 d = acc[ni];
            h3s[r * 72 + o0] = __float2half_rn(fmaxf((d.x + bia0) * s0 + t0, 0.f));
            h3s[r * 72 + o1] = __float2half_rn(fmaxf((d.y + bia1) * s1 + t1, 0.f));
            h3s[(r + 8) * 72 + o0] = __float2half_rn(fmaxf((d.z + bia0) * s0 + t0, 0.f));
            h3s[(r + 8) * 72 + o1] = __float2half_rn(fmaxf((d.w + bia1) * s1 + t1, 0.f));
        }
    }
    __syncthreads();

    // ---- phase 3: c3  M64 K64 N128 + residual + relu -> ys (aliases c1ws) ----
    {
        int n_base = (w >> 2) * 64;
        float4 acc[8];
#pragma unroll
        for (int ni = 0; ni < 8; ni++) acc[ni] = make_float4(0.f,0.f,0.f,0.f);
#pragma unroll
        for (int ks = 0; ks < 4; ks++) {
            int kb = ks * 16;
            uint32_t afr[4];
            int r = m_base + g;
            afr[0] = lds_u32(&h3s[r * 72 + kb + 2*tg]);
            afr[1] = lds_u32(&h3s[(r + 8) * 72 + kb + 2*tg]);
            afr[2] = lds_u32(&h3s[r * 72 + kb + 2*tg + 8]);
            afr[3] = lds_u32(&h3s[(r + 8) * 72 + kb + 2*tg + 8]);
            uint32_t bfr[8][2];
#pragma unroll
            for (int ni = 0; ni < 8; ni++) {
                int c = n_base + ni * 8 + g;
                bfr[ni][0] = lds_u32(&c3ws[c * 72 + kb + 2*tg]);
                bfr[ni][1] = lds_u32(&c3ws[c * 72 + kb + 2*tg + 8]);
            }
#pragma unroll
            for (int ni = 0; ni < 8; ni++)
                mma_f16(acc[ni], afr, bfr[ni]);
        }
        __syncthreads();   // ensure no warp still reads c1ws region before ys overwrite
        int r = m_base + g, r2 = r + 8;
        int l1 = lb, p1 = g;
        int l2 = lb + 1, p2 = g;
        size_t gr1 = (size_t)(r0 + r) * DLOI, gr2 = (size_t)(r0 + r2) * DLOI;
#pragma unroll
        for (int ni = 0; ni < 8; ni++) {
            int o0 = n_base + ni * 8 + 2 * tg, o1 = o0 + 1;
            float bia0 = __ldg(&c3b[o0]), bia1 = __ldg(&c3b[o1]);
            float4 d = acc[ni];
            ys[l1 * 1024 + o0 * 8 + p1] = __float2half_rn(
                fmaxf(d.x + bia0 + __half2float(__ldg(&g_xph[gr1 + o0])), 0.f));
            ys[l1 * 1024 + o1 * 8 + p1] = __float2half_rn(
                fmaxf(d.y + bia1 + __half2float(__ldg(&g_xph[gr1 + o1])), 0.f));
            ys[l2 * 1024 + o0 * 8 + p2] = __float2half_rn(
                fmaxf(d.z + bia0 + __half2float(__ldg(&g_xph[gr2 + o0])), 0.f));
            ys[l2 * 1024 + o1 * 8 + p2] = __float2half_rn(
                fmaxf(d.w + bia1 + __half2float(__ldg(&g_xph[gr2 + o1])), 0.f));
        }
    }
    __syncthreads();

    // ---- phase 4: fc2 + softmax, warp per line ----
    {
        const __half* Y = ys + w * 1024;
        float s0 = 0.f, s1 = 0.f, s2 = 0.f, s3 = 0.f;
#pragma unroll
        for (int j = 0; j < 8; j++) {
            int idx = lane * 4 + j * 128;
            float2 ya = __half22float2(*(const __half2*)&Y[idx]);
            float2 yb = __half22float2(*(const __half2*)&Y[idx + 2]);
            float2 w0a = __half22float2(*(const __half2*)&wfh[idx]);
            float2 w0b = __half22float2(*(const __half2*)&wfh[idx + 2]);
            float2 w1a = __half22float2(*(const __half2*)&wfh[1024 + idx]);
            float2 w1b = __half22float2(*(const __half2*)&wfh[1024 + idx + 2]);
            float2 w2a = __half22float2(*(const __half2*)&wfh[2048 + idx]);
            float2 w2b = __half22float2(*(const __half2*)&wfh[2048 + idx + 2]);
            float2 w3a = __half22float2(*(const __half2*)&wfh[3072 + idx]);
            float2 w3b = __half22float2(*(const __half2*)&wfh[3072 + idx + 2]);
            s0 += ya.x * w0a.x + ya.y * w0a.y + yb.x * w0b.x + yb.y * w0b.y;
            s1 += ya.x * w1a.x + ya.y * w1a.y + yb.x * w1b.x + yb.y * w1b.y;
            s2 += ya.x * w2a.x + ya.y * w2a.y + yb.x * w2b.x + yb.y * w2b.y;
            s3 += ya.x * w3a.x + ya.y * w3a.y + yb.x * w3b.x + yb.y * w3b.y;
        }
#pragma unroll
        for (int off = 16; off; off >>= 1) {
            s0 += __shfl_down_sync(0xffffffffu, s0, off);
            s1 += __shfl_down_sync(0xffffffffu, s1, off);
            s2 += __shfl_down_sync(0xffffffffu, s2, off);
            s3 += __shfl_down_sync(0xffffffffu, s3, off);
        }
        if (lane == 0) {
            int n = blockIdx.x * 8 + w;
            float z0 = s0 + __ldg(&bfc2[0]), z1 = s1 + __ldg(&bfc2[1]);
            float z2 = s2 + __ldg(&bfc2[2]), z3 = s3 + __ldg(&bfc2[3]);
            float m = fmaxf(fmaxf(z0, z1), fmaxf(z2, z3));
            float e0 = expf(z0 - m), e1 = expf(z1 - m), e2 = expf(z2 - m), e3 = expf(z3 - m);
            float inv = 1.0f / (e0 + e1 + e2 + e3);
            *(float4*)&out[(size_t)n * 4] = make_float4(e0 * inv, e1 * inv, e2 * inv, e3 * inv);
        }
    }
}

// ---------------- launch ----------------
extern "C" void kernel_launch(void* const* d_in, const int* in_sizes, int n_in,
                              void* d_out, int out_size)
{
    const float* feature = (const float*)d_in[0];
    const float* lines   = (const float*)d_in[1];
    const float* w_fc1   = (const float*)d_in[2];
    const float* b_fc1   = (const float*)d_in[3];
    const float* bn1     = (const float*)d_in[4];
    const float* c1_w    = (const float*)d_in[5];
    const float* c1_b    = (const float*)d_in[6];
    const float* bn2     = (const float*)d_in[7];
    const float* c2_w    = (const float*)d_in[8];
    const float* c2_b    = (const float*)d_in[9];
    const float* bn3     = (const float*)d_in[10];
    const float* c3_w    = (const float*)d_in[11];
    const float* c3_b    = (const float*)d_in[12];
    const float* w_fc2   = (const float*)d_in[13];
    const float* b_fc2   = (const float*)d_in[14];
    float* out = (float*)d_out;

    static int attr_set = 0;
    if (!attr_set) {
        cudaFuncSetAttribute(fc1_gemm_tf32, cudaFuncAttributeMaxDynamicSharedMemorySize, FC1_SMEM);
        cudaFuncSetAttribute(bottleneck_fused, cudaFuncAttributeMaxDynamicSharedMemorySize, FB_SMEM);
        attr_set = 1;
    }

    prep_kernel<<<64, 256>>>(w_fc1, bn1, c1_w, bn2, c2_w, bn3, c3_w, w_fc2);

    dim3 grid(HW / 256, BQ);
    fc1_gemm_tf32<<<grid, 256, FC1_SMEM>>>(feature, b_fc1);

    line_gather<<<NL, 128>>>(lines);
    bottleneck_fused<<<RROWS / 64, 256, FB_SMEM>>>(c1_b, c2_b, c3_b, b_fc2, out);
}